// round 2
// baseline (speedup 1.0000x reference)
#include <cuda_runtime.h>

#define NPTS   65536
#define BATCH  2
#define ROWS   (BATCH*NPTS)
#define DIM    35
#define KNN    16
#define CH8    8
#define CH32   32
#define OUTCH  128
#define EPSF   1e-5f

// Folded constants computed once per launch by setup_kernel.
struct Consts {
    float gWs[DIM*CH32];   // gamma_W * s_gamma  (35 x 32)
    float tg[CH32];        // gamma bn bias
    float PA[3*CH8];       // (point_W[1+i] + point_W[7+i]) * s_p  (p coefficients)
    float PB[3*CH8];       // (point_W[4+i] - point_W[7+i]) * s_p  (pn coefficients)
    float w0[CH8];         // point_W[0] * s_p (dd coefficient)
    float tp[CH8];         // point bn bias
    float mwP[CH8];        // map_W[0:8] * s_map  (point slice of map weights)
    float u[32];           // eta collapse:  e_map = feat . u
    float vv[32];          // mu  collapse:  m_map = pnf  . v
    float K0;              // t_map + t_eta.mwE + t_mu.mwM
};
__device__ Consts g_c;

// Per-row precomputed tables (pass 1 outputs)
__device__ __align__(16) float  g_gam[(size_t)ROWS*CH32];  // 16.8 MB, fits L2
__device__ __align__(16) float4 g_nbrA[ROWS];              // {pn.x, pn.y, pn.z, |pn|^2}
__device__ float  g_mm[ROWS];              // m_map per row
__device__ float  g_em[ROWS];              // e_map per row
__device__ int    g_idx_is32;              // 1 if idx buffer is int32, 0 if int64

// ---------------------------------------------------------------------------
// Probe: detect idx dtype. If interpreted-as-int64 values are out of range,
// the buffer is really int32 (JAX x64-disabled downgrades int64 -> int32).
// ---------------------------------------------------------------------------
__global__ void probe_kernel(const long long* __restrict__ idx64)
{
    if (threadIdx.x == 0 && blockIdx.x == 0) {
        int is32 = 0;
        for (int i = 0; i < 1024; i++) {
            long long v = idx64[i];
            if (v < 0 || v >= NPTS) { is32 = 1; break; }
        }
        g_idx_is32 = is32;
    }
}

// ---------------------------------------------------------------------------
// Setup: fold all batch norms into weights; collapse eta/mu paths to vectors.
// ---------------------------------------------------------------------------
__global__ void setup_kernel(
    const float* __restrict__ point_W, const float* __restrict__ point_bn,
    const float* __restrict__ eta_W,   const float* __restrict__ eta_bn,
    const float* __restrict__ mu_W,    const float* __restrict__ mu_bn,
    const float* __restrict__ gamma_W, const float* __restrict__ gamma_bn,
    const float* __restrict__ map_W,   const float* __restrict__ map_bn)
{
    int tid = threadIdx.x;
    float s_map = map_bn[0] * rsqrtf(map_bn[3] + EPSF);
    float t_map = map_bn[1] - map_bn[2] * s_map;

    // gamma fold: gWs[d][c] = gamma_W[d][c] * s_g[c]
    for (int i = tid; i < DIM*CH32; i += blockDim.x) {
        int c = i & 31;
        float sg = gamma_bn[0*CH32+c] * rsqrtf(gamma_bn[3*CH32+c] + EPSF);
        g_c.gWs[i] = gamma_W[i] * sg;
    }
    if (tid < CH32) {
        int c = tid;
        float sg = gamma_bn[0*CH32+c] * rsqrtf(gamma_bn[3*CH32+c] + EPSF);
        g_c.tg[c] = gamma_bn[1*CH32+c] - gamma_bn[2*CH32+c] * sg;
    }
    // eta/mu collapse vectors u, v  (feature index i in [0,32))
    if (tid < 32) {
        int i = tid;
        float su = 0.f, sv = 0.f;
        for (int c = 0; c < CH8; c++) {
            float se  = eta_bn[0*CH8+c] * rsqrtf(eta_bn[3*CH8+c] + EPSF);
            float smu = mu_bn [0*CH8+c] * rsqrtf(mu_bn [3*CH8+c] + EPSF);
            float mwE = map_W[1*CH8+c] * s_map;
            float mwM = map_W[2*CH8+c] * s_map;
            su += eta_W[i*CH8+c] * se  * mwE;
            sv += mu_W [i*CH8+c] * smu * mwM;
        }
        g_c.u[i]  = su;
        g_c.vv[i] = sv;
    }
    // point fold
    if (tid < CH8) {
        int c = tid;
        float sp  = point_bn[0*CH8+c] * rsqrtf(point_bn[3*CH8+c] + EPSF);
        float tpv = point_bn[1*CH8+c] - point_bn[2*CH8+c] * sp;
        g_c.w0[c] = point_W[0*CH8+c] * sp;
        #pragma unroll
        for (int i = 0; i < 3; i++) {
            g_c.PA[i*CH8+c] = (point_W[(1+i)*CH8+c] + point_W[(7+i)*CH8+c]) * sp;
            g_c.PB[i*CH8+c] = (point_W[(4+i)*CH8+c] - point_W[(7+i)*CH8+c]) * sp;
        }
        g_c.tp[c]  = tpv;
        g_c.mwP[c] = map_W[c] * s_map;
    }
    if (tid == 0) {
        float k0 = t_map;
        for (int c = 0; c < CH8; c++) {
            float se  = eta_bn[0*CH8+c] * rsqrtf(eta_bn[3*CH8+c] + EPSF);
            float te  = eta_bn[1*CH8+c] - eta_bn[2*CH8+c] * se;
            float smu = mu_bn [0*CH8+c] * rsqrtf(mu_bn [3*CH8+c] + EPSF);
            float tmu = mu_bn [1*CH8+c] - mu_bn [2*CH8+c] * smu;
            k0 += te  * map_W[1*CH8+c] * s_map;
            k0 += tmu * map_W[2*CH8+c] * s_map;
        }
        g_c.K0 = k0;
    }
}

// ---------------------------------------------------------------------------
// Pass 1: per-row precompute — gam[32], m_map, e_map, pn, |pn|^2.
// 128 threads/block, 2 rows/thread, 256 rows/block, coalesced row staging.
// ---------------------------------------------------------------------------
__global__ void __launch_bounds__(128) pass1_kernel(const float* __restrict__ feats)
{
    __shared__ __align__(16) float srow[256*DIM + 1];  // 35844 B, staged coalesced
    __shared__ float sW[DIM*CH32];                     // folded gamma weights
    __shared__ float stg[CH32], su[32], sv[32];
    int tid = threadIdx.x;
    int R0  = blockIdx.x * 256;

    const float4* src = (const float4*)feats + ((size_t)R0 * DIM >> 2);
    float4* dst = (float4*)srow;
    for (int i = tid; i < 256*DIM/4; i += 128) dst[i] = src[i];
    for (int i = tid; i < DIM*CH32; i += 128) sW[i] = g_c.gWs[i];
    if (tid < CH32) stg[tid] = g_c.tg[tid];
    if (tid < 32) { su[tid] = g_c.u[tid]; sv[tid] = g_c.vv[tid]; }
    __syncthreads();

    float acc0[CH32], acc1[CH32];
    #pragma unroll
    for (int c = 0; c < CH32; c++) { acc0[c] = stg[c]; acc1[c] = stg[c]; }

    const float* r0 = &srow[tid * DIM];
    const float* r1 = &srow[(tid + 128) * DIM];
    float pn0[3], pn1[3];
    float S0 = 0.f, S1 = 0.f, e0 = 0.f, e1 = 0.f, m0 = 0.f, m1 = 0.f;

    #pragma unroll
    for (int d = 0; d < 3; d++) {
        float f0 = r0[d], f1 = r1[d];
        pn0[d] = f0; pn1[d] = f1;
        S0 = fmaf(f0, f0, S0); S1 = fmaf(f1, f1, S1);
        #pragma unroll
        for (int c = 0; c < CH32; c++) {
            float w = sW[d*CH32 + c];
            acc0[c] = fmaf(f0, w, acc0[c]);
            acc1[c] = fmaf(f1, w, acc1[c]);
        }
    }
    for (int d = 3; d < DIM; d++) {
        float f0 = r0[d], f1 = r1[d];
        float uu = su[d-3], vw = sv[d-3];
        e0 = fmaf(f0, uu, e0); e1 = fmaf(f1, uu, e1);
        m0 = fmaf(f0, vw, m0); m1 = fmaf(f1, vw, m1);
        #pragma unroll
        for (int c = 0; c < CH32; c++) {
            float w = sW[d*CH32 + c];
            acc0[c] = fmaf(f0, w, acc0[c]);
            acc1[c] = fmaf(f1, w, acc1[c]);
        }
    }

    int gr0 = R0 + tid, gr1 = R0 + tid + 128;
    float4* gp0 = (float4*)&g_gam[(size_t)gr0 * CH32];
    float4* gp1 = (float4*)&g_gam[(size_t)gr1 * CH32];
    #pragma unroll
    for (int q = 0; q < 8; q++) {
        gp0[q] = make_float4(acc0[4*q], acc0[4*q+1], acc0[4*q+2], acc0[4*q+3]);
        gp1[q] = make_float4(acc1[4*q], acc1[4*q+1], acc1[4*q+2], acc1[4*q+3]);
    }
    g_nbrA[gr0] = make_float4(pn0[0], pn0[1], pn0[2], S0);
    g_nbrA[gr1] = make_float4(pn1[0], pn1[1], pn1[2], S1);
    g_mm[gr0] = m0; g_mm[gr1] = m1;
    g_em[gr0] = e0; g_em[gr1] = e1;
}

// ---------------------------------------------------------------------------
// Pass 2: warp per point. lanes 0..15 compute the map scalar g_k for one
// neighbor each; then channel-per-lane gathers gam rows (coalesced 128B) and
// max-reduces; then fc matvec from smem (4 outputs/lane).
// ---------------------------------------------------------------------------
__global__ void __launch_bounds__(256) pass2_kernel(
    const float* __restrict__ feats, const void* __restrict__ idx_raw,
    const float* __restrict__ fcW, float* __restrict__ out, int nwarps)
{
    __shared__ __align__(16) float4 sfc[CH32*32];   // fc_W (32x128) = 16 KB
    int tid = threadIdx.x;
    const float4* fsrc = (const float4*)fcW;
    for (int i = tid; i < CH32*32; i += 256) sfc[i] = fsrc[i];
    __syncthreads();

    const int is32 = g_idx_is32;
    const int*       idx32 = (const int*)idx_raw;
    const long long* idx64 = (const long long*)idx_raw;

    // hoist folded constants into registers (loop-invariant across points)
    float w0r[CH8], PB0[CH8], PB1[CH8], PB2[CH8], mwr[CH8];
    float tpr[CH8], PA0[CH8], PA1[CH8], PA2[CH8];
    #pragma unroll
    for (int c = 0; c < CH8; c++) {
        w0r[c] = g_c.w0[c];  mwr[c] = g_c.mwP[c]; tpr[c] = g_c.tp[c];
        PA0[c] = g_c.PA[0*CH8+c]; PA1[c] = g_c.PA[1*CH8+c]; PA2[c] = g_c.PA[2*CH8+c];
        PB0[c] = g_c.PB[0*CH8+c]; PB1[c] = g_c.PB[1*CH8+c]; PB2[c] = g_c.PB[2*CH8+c];
    }
    float K0 = g_c.K0;

    int lane = tid & 31;
    int gw = blockIdx.x * 8 + (tid >> 5);

    for (int pi = gw; pi < ROWS; pi += nwarps) {
        int bbase = pi & ~(NPTS - 1);            // b * N (N = 2^16)
        const float* fp = feats + (size_t)pi * DIM;
        float p0 = __ldg(fp), p1 = __ldg(fp+1), p2 = __ldg(fp+2);
        float Sp = p0*p0 + p1*p1 + p2*p2;
        float em = g_em[pi];

        float base[CH8];
        #pragma unroll
        for (int c = 0; c < CH8; c++)
            base[c] = tpr[c] + p0*PA0[c] + p1*PA1[c] + p2*PA2[c];

        float g = 0.f; int j = 0;
        if (lane < KNN) {
            size_t off = (size_t)pi * KNN + lane;
            int jv = is32 ? idx32[off] : (int)idx64[off];
            j = bbase + jv;
            float4 a = g_nbrA[j];
            float mm = g_mm[j];
            float t = Sp + a.w - 2.f * (p0*a.x + p1*a.y + p2*a.z);   // |p-pn|^2
            float pt = 0.f;
            #pragma unroll
            for (int c = 0; c < CH8; c++) {
                float h = fmaf(w0r[c], t, base[c]);
                h = fmaf(a.x, PB0[c], h);
                h = fmaf(a.y, PB1[c], h);
                h = fmaf(a.z, PB2[c], h);
                h = fmaxf(h, 0.f);                 // relu(point bn)
                pt = fmaf(h, mwr[c], pt);
            }
            g = fmaxf(pt + em + mm + K0, 0.f);     // relu(map bn)
        }

        // channel-per-lane max over 16 neighbors; gam rows are coalesced 128 B
        float m = -3.402823466e38f;
        #pragma unroll
        for (int k = 0; k < KNN; k++) {
            int   jk = __shfl_sync(0xffffffffu, j, k);
            float gk = __shfl_sync(0xffffffffu, g, k);
            float gv = g_gam[(size_t)jk * CH32 + lane];
            m = fmaxf(m, gk * gv);
        }

        // fc: out[128] = m[32] @ fc_W(32,128); 4 outputs per lane
        float4 acc = make_float4(0.f, 0.f, 0.f, 0.f);
        #pragma unroll
        for (int c = 0; c < CH32; c++) {
            float mc = __shfl_sync(0xffffffffu, m, c);
            float4 w = sfc[c*32 + lane];
            acc.x = fmaf(mc, w.x, acc.x);
            acc.y = fmaf(mc, w.y, acc.y);
            acc.z = fmaf(mc, w.z, acc.z);
            acc.w = fmaf(mc, w.w, acc.w);
        }
        ((float4*)out)[(size_t)pi * 32 + lane] = acc;
    }
}

extern "C" void kernel_launch(void* const* d_in, const int* in_sizes, int n_in,
                              void* d_out, int out_size)
{
    const float* feats    = (const float*)d_in[0];
    const void*  idx_raw  = (const void*)d_in[1];
    const float* point_W  = (const float*)d_in[2];
    const float* point_bn = (const float*)d_in[3];
    const float* eta_W    = (const float*)d_in[4];
    const float* eta_bn   = (const float*)d_in[5];
    const float* mu_W     = (const float*)d_in[6];
    const float* mu_bn    = (const float*)d_in[7];
    const float* gamma_W  = (const float*)d_in[8];
    const float* gamma_bn = (const float*)d_in[9];
    const float* map_W    = (const float*)d_in[10];
    const float* map_bn   = (const float*)d_in[11];
    const float* fc_W     = (const float*)d_in[12];
    float* out = (float*)d_out;

    probe_kernel<<<1, 32>>>((const long long*)idx_raw);
    setup_kernel<<<1, 256>>>(point_W, point_bn, eta_W, eta_bn, mu_W, mu_bn,
                             gamma_W, gamma_bn, map_W, map_bn);
    pass1_kernel<<<ROWS/256, 128>>>(feats);
    const int blocks = 1184;   // 8 SM-saturating waves of warps, grid-stride
    pass2_kernel<<<blocks, 256>>>(feats, idx_raw, fc_W, out, blocks * 8);
}

// round 3
// speedup vs baseline: 1.3623x; 1.3623x over previous
#include <cuda_runtime.h>

#define NPTS   65536
#define BATCH  2
#define ROWS   (BATCH*NPTS)
#define DIM    35
#define KNN    16
#define CH8    8
#define CH32   32
#define OUTCH  128
#define EPSF   1e-5f

// Folded constants computed once per launch by setup_kernel.
struct Consts {
    float gWs[DIM*CH32];   // gamma_W * s_gamma  (35 x 32)
    float tg[CH32];        // gamma bn bias
    float PA[3*CH8];       // (point_W[1+i] + point_W[7+i]) * s_p  (p coefficients)
    float PB[3*CH8];       // (point_W[4+i] - point_W[7+i]) * s_p  (pn coefficients)
    float w0[CH8];         // point_W[0] * s_p (dd coefficient)
    float tp[CH8];         // point bn bias
    float mwP[CH8];        // map_W[0:8] * s_map  (point slice of map weights)
    float u[32];           // eta collapse:  e_map = feat . u
    float vv[32];          // mu  collapse:  m_map = pnf  . v
    float K0;              // t_map + t_eta.mwE + t_mu.mwM
};
__device__ Consts g_c;

// Per-row precomputed tables (pass 1 outputs)
__device__ __align__(16) float  g_gam[(size_t)ROWS*CH32];  // 16.8 MB, fits L2
__device__ __align__(16) float4 g_nbrA[ROWS];              // {pn.x, pn.y, pn.z, |pn|^2}
__device__ float  g_mm[ROWS];              // m_map per row
__device__ float  g_em[ROWS];              // e_map per row
__device__ int    g_idx_is32;              // 1 if idx buffer is int32, 0 if int64

// ---------------------------------------------------------------------------
// Setup: probe idx dtype (warp 0, parallel), fold all batch norms into
// weights, collapse eta/mu paths to vectors.
// ---------------------------------------------------------------------------
__global__ void setup_kernel(
    const long long* __restrict__ idx64,
    const float* __restrict__ point_W, const float* __restrict__ point_bn,
    const float* __restrict__ eta_W,   const float* __restrict__ eta_bn,
    const float* __restrict__ mu_W,    const float* __restrict__ mu_bn,
    const float* __restrict__ gamma_W, const float* __restrict__ gamma_bn,
    const float* __restrict__ map_W,   const float* __restrict__ map_bn)
{
    int tid = threadIdx.x;

    // dtype probe: if ANY of 32 sampled int64 views is out of range, it's int32.
    // (If the buffer is really int32, a sampled int64 looks valid w.p. ~1.5e-5.)
    if (tid < 32) {
        long long v = idx64[tid];
        unsigned bad = __ballot_sync(0xffffffffu, v < 0 || v >= NPTS);
        if (tid == 0) g_idx_is32 = bad ? 1 : 0;
    }

    float s_map = map_bn[0] * rsqrtf(map_bn[3] + EPSF);
    float t_map = map_bn[1] - map_bn[2] * s_map;

    // gamma fold: gWs[d][c] = gamma_W[d][c] * s_g[c]
    for (int i = tid; i < DIM*CH32; i += blockDim.x) {
        int c = i & 31;
        float sg = gamma_bn[0*CH32+c] * rsqrtf(gamma_bn[3*CH32+c] + EPSF);
        g_c.gWs[i] = gamma_W[i] * sg;
    }
    if (tid < CH32) {
        int c = tid;
        float sg = gamma_bn[0*CH32+c] * rsqrtf(gamma_bn[3*CH32+c] + EPSF);
        g_c.tg[c] = gamma_bn[1*CH32+c] - gamma_bn[2*CH32+c] * sg;
    }
    // eta/mu collapse vectors u, v  (feature index i in [0,32))
    if (tid < 32) {
        int i = tid;
        float su = 0.f, sv = 0.f;
        for (int c = 0; c < CH8; c++) {
            float se  = eta_bn[0*CH8+c] * rsqrtf(eta_bn[3*CH8+c] + EPSF);
            float smu = mu_bn [0*CH8+c] * rsqrtf(mu_bn [3*CH8+c] + EPSF);
            float mwE = map_W[1*CH8+c] * s_map;
            float mwM = map_W[2*CH8+c] * s_map;
            su += eta_W[i*CH8+c] * se  * mwE;
            sv += mu_W [i*CH8+c] * smu * mwM;
        }
        g_c.u[i]  = su;
        g_c.vv[i] = sv;
    }
    // point fold
    if (tid < CH8) {
        int c = tid;
        float sp  = point_bn[0*CH8+c] * rsqrtf(point_bn[3*CH8+c] + EPSF);
        float tpv = point_bn[1*CH8+c] - point_bn[2*CH8+c] * sp;
        g_c.w0[c] = point_W[0*CH8+c] * sp;
        #pragma unroll
        for (int i = 0; i < 3; i++) {
            g_c.PA[i*CH8+c] = (point_W[(1+i)*CH8+c] + point_W[(7+i)*CH8+c]) * sp;
            g_c.PB[i*CH8+c] = (point_W[(4+i)*CH8+c] - point_W[(7+i)*CH8+c]) * sp;
        }
        g_c.tp[c]  = tpv;
        g_c.mwP[c] = map_W[c] * s_map;
    }
    if (tid == 0) {
        float k0 = t_map;
        for (int c = 0; c < CH8; c++) {
            float se  = eta_bn[0*CH8+c] * rsqrtf(eta_bn[3*CH8+c] + EPSF);
            float te  = eta_bn[1*CH8+c] - eta_bn[2*CH8+c] * se;
            float smu = mu_bn [0*CH8+c] * rsqrtf(mu_bn [3*CH8+c] + EPSF);
            float tmu = mu_bn [1*CH8+c] - mu_bn [2*CH8+c] * smu;
            k0 += te  * map_W[1*CH8+c] * s_map;
            k0 += tmu * map_W[2*CH8+c] * s_map;
        }
        g_c.K0 = k0;
    }
}

// ---------------------------------------------------------------------------
// Pass 1: per-row precompute — gam[32], m_map, e_map, pn, |pn|^2.
// ---------------------------------------------------------------------------
__global__ void __launch_bounds__(128) pass1_kernel(const float* __restrict__ feats)
{
    __shared__ __align__(16) float srow[256*DIM + 1];  // staged coalesced
    __shared__ float sW[DIM*CH32];                     // folded gamma weights
    __shared__ float stg[CH32], su[32], sv[32];
    int tid = threadIdx.x;
    int R0  = blockIdx.x * 256;

    const float4* src = (const float4*)feats + ((size_t)R0 * DIM >> 2);
    float4* dst = (float4*)srow;
    for (int i = tid; i < 256*DIM/4; i += 128) dst[i] = src[i];
    for (int i = tid; i < DIM*CH32; i += 128) sW[i] = g_c.gWs[i];
    if (tid < CH32) stg[tid] = g_c.tg[tid];
    if (tid < 32) { su[tid] = g_c.u[tid]; sv[tid] = g_c.vv[tid]; }
    __syncthreads();

    float acc0[CH32], acc1[CH32];
    #pragma unroll
    for (int c = 0; c < CH32; c++) { acc0[c] = stg[c]; acc1[c] = stg[c]; }

    const float* r0 = &srow[tid * DIM];
    const float* r1 = &srow[(tid + 128) * DIM];
    float pn0[3], pn1[3];
    float S0 = 0.f, S1 = 0.f, e0 = 0.f, e1 = 0.f, m0 = 0.f, m1 = 0.f;

    #pragma unroll
    for (int d = 0; d < 3; d++) {
        float f0 = r0[d], f1 = r1[d];
        pn0[d] = f0; pn1[d] = f1;
        S0 = fmaf(f0, f0, S0); S1 = fmaf(f1, f1, S1);
        #pragma unroll
        for (int c = 0; c < CH32; c++) {
            float w = sW[d*CH32 + c];
            acc0[c] = fmaf(f0, w, acc0[c]);
            acc1[c] = fmaf(f1, w, acc1[c]);
        }
    }
    for (int d = 3; d < DIM; d++) {
        float f0 = r0[d], f1 = r1[d];
        float uu = su[d-3], vw = sv[d-3];
        e0 = fmaf(f0, uu, e0); e1 = fmaf(f1, uu, e1);
        m0 = fmaf(f0, vw, m0); m1 = fmaf(f1, vw, m1);
        #pragma unroll
        for (int c = 0; c < CH32; c++) {
            float w = sW[d*CH32 + c];
            acc0[c] = fmaf(f0, w, acc0[c]);
            acc1[c] = fmaf(f1, w, acc1[c]);
        }
    }

    int gr0 = R0 + tid, gr1 = R0 + tid + 128;
    float4* gp0 = (float4*)&g_gam[(size_t)gr0 * CH32];
    float4* gp1 = (float4*)&g_gam[(size_t)gr1 * CH32];
    #pragma unroll
    for (int q = 0; q < 8; q++) {
        gp0[q] = make_float4(acc0[4*q], acc0[4*q+1], acc0[4*q+2], acc0[4*q+3]);
        gp1[q] = make_float4(acc1[4*q], acc1[4*q+1], acc1[4*q+2], acc1[4*q+3]);
    }
    g_nbrA[gr0] = make_float4(pn0[0], pn0[1], pn0[2], S0);
    g_nbrA[gr1] = make_float4(pn1[0], pn1[1], pn1[2], S1);
    g_mm[gr0] = m0; g_mm[gr1] = m1;
    g_em[gr0] = e0; g_em[gr1] = e1;
}

// ---------------------------------------------------------------------------
// Pass 2: warp = 4 consecutive points. Two half-warp compute phases (lanes
// 0-15 = point A, 16-31 = point B) produce g per neighbor; channel-per-lane
// gather/max gives m[4]; ONE fc loop serves all 4 points (fc_W smem reads
// amortized 4x vs R2).
// ---------------------------------------------------------------------------
__global__ void __launch_bounds__(128, 3) pass2_kernel(
    const float* __restrict__ feats, const void* __restrict__ idx_raw,
    const float* __restrict__ fcW, float* __restrict__ out)
{
    __shared__ __align__(16) float4 sfc[CH32*32];   // fc_W (32x128) = 16 KB
    int tid = threadIdx.x;
    const float4* fsrc = (const float4*)fcW;
    #pragma unroll
    for (int i = 0; i < 8; i++) sfc[tid + 128*i] = fsrc[tid + 128*i];
    __syncthreads();

    const int is32 = g_idx_is32;
    const int*       idx32 = (const int*)idx_raw;
    const long long* idx64 = (const long long*)idx_raw;

    // hoist folded constants into registers
    float w0r[CH8], PB0[CH8], PB1[CH8], PB2[CH8], mwr[CH8];
    float tpr[CH8], PA0[CH8], PA1[CH8], PA2[CH8];
    #pragma unroll
    for (int c = 0; c < CH8; c++) {
        w0r[c] = g_c.w0[c];  mwr[c] = g_c.mwP[c]; tpr[c] = g_c.tp[c];
        PA0[c] = g_c.PA[0*CH8+c]; PA1[c] = g_c.PA[1*CH8+c]; PA2[c] = g_c.PA[2*CH8+c];
        PB0[c] = g_c.PB[0*CH8+c]; PB1[c] = g_c.PB[1*CH8+c]; PB2[c] = g_c.PB[2*CH8+c];
    }
    const float K0 = g_c.K0;

    int lane = tid & 31;
    int l16  = lane & 15;
    int half = lane >> 4;                       // 0 or 1
    int p0   = (blockIdx.x * 4 + (tid >> 5)) * 4;   // 4 points per warp

    float m[4];

    #pragma unroll
    for (int pair = 0; pair < 2; pair++) {
        int pMine = p0 + pair*2 + half;         // this lane's point
        int bbase = pMine & ~(NPTS - 1);        // b * N

        const float* fp = feats + (size_t)pMine * DIM;
        float px = __ldg(fp), py = __ldg(fp+1), pz = __ldg(fp+2);
        float Sp = px*px + py*py + pz*pz;
        float em = g_em[pMine];

        // neighbor index + per-neighbor compute (all 32 lanes active)
        size_t off = (size_t)pMine * KNN + l16;
        int jv = is32 ? idx32[off] : (int)idx64[off];
        int j = bbase + jv;
        float4 a = g_nbrA[j];
        float mm = g_mm[j];
        float t = Sp + a.w - 2.f * (px*a.x + py*a.y + pz*a.z);   // |p-pn|^2
        float pt = 0.f;
        #pragma unroll
        for (int c = 0; c < CH8; c++) {
            float h = tpr[c];
            h = fmaf(px, PA0[c], h);
            h = fmaf(py, PA1[c], h);
            h = fmaf(pz, PA2[c], h);
            h = fmaf(w0r[c], t, h);
            h = fmaf(a.x, PB0[c], h);
            h = fmaf(a.y, PB1[c], h);
            h = fmaf(a.z, PB2[c], h);
            h = fmaxf(h, 0.f);                 // relu(point bn)
            pt = fmaf(h, mwr[c], pt);
        }
        float g = fmaxf(pt + em + mm + K0, 0.f);   // relu(map bn)

        // channel-per-lane max over 16 neighbors, both points of the pair
        float mA = -3.402823466e38f, mB = -3.402823466e38f;
        #pragma unroll
        for (int k = 0; k < KNN; k++) {
            int   jA = __shfl_sync(0xffffffffu, j, k);
            float gA = __shfl_sync(0xffffffffu, g, k);
            int   jB = __shfl_sync(0xffffffffu, j, k + 16);
            float gB = __shfl_sync(0xffffffffu, g, k + 16);
            float vA = *(const float*)((const char*)g_gam + (((size_t)(unsigned)jA << 7) + ((unsigned)lane << 2)));
            float vB = *(const float*)((const char*)g_gam + (((size_t)(unsigned)jB << 7) + ((unsigned)lane << 2)));
            mA = fmaxf(mA, gA * vA);
            mB = fmaxf(mB, gB * vB);
        }
        m[pair*2]     = mA;
        m[pair*2 + 1] = mB;
    }

    // fc for all 4 points: out[128] = m[32] @ fc_W(32,128); 4 outs/lane/point
    float4 acc0 = make_float4(0.f,0.f,0.f,0.f);
    float4 acc1 = acc0, acc2 = acc0, acc3 = acc0;
    #pragma unroll
    for (int c = 0; c < CH32; c++) {
        float4 w = sfc[c*32 + lane];
        float m0 = __shfl_sync(0xffffffffu, m[0], c);
        float m1 = __shfl_sync(0xffffffffu, m[1], c);
        float m2 = __shfl_sync(0xffffffffu, m[2], c);
        float m3 = __shfl_sync(0xffffffffu, m[3], c);
        acc0.x = fmaf(m0, w.x, acc0.x); acc0.y = fmaf(m0, w.y, acc0.y);
        acc0.z = fmaf(m0, w.z, acc0.z); acc0.w = fmaf(m0, w.w, acc0.w);
        acc1.x = fmaf(m1, w.x, acc1.x); acc1.y = fmaf(m1, w.y, acc1.y);
        acc1.z = fmaf(m1, w.z, acc1.z); acc1.w = fmaf(m1, w.w, acc1.w);
        acc2.x = fmaf(m2, w.x, acc2.x); acc2.y = fmaf(m2, w.y, acc2.y);
        acc2.z = fmaf(m2, w.z, acc2.z); acc2.w = fmaf(m2, w.w, acc2.w);
        acc3.x = fmaf(m3, w.x, acc3.x); acc3.y = fmaf(m3, w.y, acc3.y);
        acc3.z = fmaf(m3, w.z, acc3.z); acc3.w = fmaf(m3, w.w, acc3.w);
    }
    float4* op = (float4*)out + (size_t)p0 * 32 + lane;
    op[0]  = acc0;
    op[32] = acc1;
    op[64] = acc2;
    op[96] = acc3;
}

extern "C" void kernel_launch(void* const* d_in, const int* in_sizes, int n_in,
                              void* d_out, int out_size)
{
    const float* feats    = (const float*)d_in[0];
    const void*  idx_raw  = (const void*)d_in[1];
    const float* point_W  = (const float*)d_in[2];
    const float* point_bn = (const float*)d_in[3];
    const float* eta_W    = (const float*)d_in[4];
    const float* eta_bn   = (const float*)d_in[5];
    const float* mu_W     = (const float*)d_in[6];
    const float* mu_bn    = (const float*)d_in[7];
    const float* gamma_W  = (const float*)d_in[8];
    const float* gamma_bn = (const float*)d_in[9];
    const float* map_W    = (const float*)d_in[10];
    const float* map_bn   = (const float*)d_in[11];
    const float* fc_W     = (const float*)d_in[12];
    float* out = (float*)d_out;

    setup_kernel<<<1, 256>>>((const long long*)idx_raw,
                             point_W, point_bn, eta_W, eta_bn, mu_W, mu_bn,
                             gamma_W, gamma_bn, map_W, map_bn);
    pass1_kernel<<<ROWS/256, 128>>>(feats);
    // 4 points/warp * 4 warps/block = 16 points/block
    pass2_kernel<<<ROWS/16, 128>>>(feats, idx_raw, fc_W, out);
}

// round 4
// speedup vs baseline: 1.3630x; 1.0005x over previous
#include <cuda_runtime.h>

#define NPTS   65536
#define BATCH  2
#define ROWS   (BATCH*NPTS)
#define DIM    35
#define KNN    16
#define CH8    8
#define CH32   32
#define OUTCH  128
#define EPSF   1e-5f

// Per-row precomputed tables (pass 1 outputs)
__device__ __align__(16) float g_gam[(size_t)ROWS*CH32];  // 16.8 MB, L2-resident
// packed neighbor record: {pn.x, pn.y, pn.z, |pn|^2, mm, pad, pad, pad} (32B)
__device__ __align__(32) float4 g_nbr[(size_t)ROWS*2];    // 4 MB
__device__ float g_em[ROWS];                              // e_map per row

// ---------------------------------------------------------------------------
// Pass 1: per-row precompute — gam[32], m_map, e_map, pn, |pn|^2.
// Folded gamma/eta/mu constants are computed per block (cheap, overlapped).
// ---------------------------------------------------------------------------
__global__ void __launch_bounds__(128) pass1_kernel(
    const float* __restrict__ feats,
    const float* __restrict__ eta_W,   const float* __restrict__ eta_bn,
    const float* __restrict__ mu_W,    const float* __restrict__ mu_bn,
    const float* __restrict__ gamma_W, const float* __restrict__ gamma_bn,
    const float* __restrict__ map_W,   const float* __restrict__ map_bn)
{
    __shared__ __align__(16) float srow[256*DIM + 1];  // staged rows
    __shared__ float sW[DIM*CH32];                     // folded gamma weights
    __shared__ float stg[CH32], su[32], sv[32];
    int tid = threadIdx.x;
    int R0  = blockIdx.x * 256;

    // stage 256 input rows coalesced
    const float4* src = (const float4*)feats + ((size_t)R0 * DIM >> 2);
    float4* dst = (float4*)srow;
    for (int i = tid; i < 256*DIM/4; i += 128) dst[i] = src[i];

    // per-block constant folding
    float s_map = map_bn[0] * rsqrtf(map_bn[3] + EPSF);
    for (int i = tid; i < DIM*CH32; i += 128) {
        int c = i & 31;
        float sg = gamma_bn[0*CH32+c] * rsqrtf(gamma_bn[3*CH32+c] + EPSF);
        sW[i] = gamma_W[i] * sg;
    }
    if (tid < CH32) {
        int c = tid;
        float sg = gamma_bn[0*CH32+c] * rsqrtf(gamma_bn[3*CH32+c] + EPSF);
        stg[c] = gamma_bn[1*CH32+c] - gamma_bn[2*CH32+c] * sg;
    }
    if (tid >= 32 && tid < 64) {
        int i = tid - 32;
        float suv = 0.f, svv = 0.f;
        for (int c = 0; c < CH8; c++) {
            float se  = eta_bn[0*CH8+c] * rsqrtf(eta_bn[3*CH8+c] + EPSF);
            float smu = mu_bn [0*CH8+c] * rsqrtf(mu_bn [3*CH8+c] + EPSF);
            suv += eta_W[i*CH8+c] * se  * (map_W[1*CH8+c] * s_map);
            svv += mu_W [i*CH8+c] * smu * (map_W[2*CH8+c] * s_map);
        }
        su[i] = suv;
        sv[i] = svv;
    }
    __syncthreads();

    float acc0[CH32], acc1[CH32];
    #pragma unroll
    for (int c = 0; c < CH32; c++) { acc0[c] = stg[c]; acc1[c] = stg[c]; }

    const float* r0 = &srow[tid * DIM];
    const float* r1 = &srow[(tid + 128) * DIM];
    float pn0[3], pn1[3];
    float S0 = 0.f, S1 = 0.f, e0 = 0.f, e1 = 0.f, m0 = 0.f, m1 = 0.f;

    #pragma unroll
    for (int d = 0; d < 3; d++) {
        float f0 = r0[d], f1 = r1[d];
        pn0[d] = f0; pn1[d] = f1;
        S0 = fmaf(f0, f0, S0); S1 = fmaf(f1, f1, S1);
        #pragma unroll
        for (int c = 0; c < CH32; c++) {
            float w = sW[d*CH32 + c];
            acc0[c] = fmaf(f0, w, acc0[c]);
            acc1[c] = fmaf(f1, w, acc1[c]);
        }
    }
    for (int d = 3; d < DIM; d++) {
        float f0 = r0[d], f1 = r1[d];
        float uu = su[d-3], vw = sv[d-3];
        e0 = fmaf(f0, uu, e0); e1 = fmaf(f1, uu, e1);
        m0 = fmaf(f0, vw, m0); m1 = fmaf(f1, vw, m1);
        #pragma unroll
        for (int c = 0; c < CH32; c++) {
            float w = sW[d*CH32 + c];
            acc0[c] = fmaf(f0, w, acc0[c]);
            acc1[c] = fmaf(f1, w, acc1[c]);
        }
    }

    int gr0 = R0 + tid, gr1 = R0 + tid + 128;
    float4* gp0 = (float4*)&g_gam[(size_t)gr0 * CH32];
    float4* gp1 = (float4*)&g_gam[(size_t)gr1 * CH32];
    #pragma unroll
    for (int q = 0; q < 8; q++) {
        gp0[q] = make_float4(acc0[4*q], acc0[4*q+1], acc0[4*q+2], acc0[4*q+3]);
        gp1[q] = make_float4(acc1[4*q], acc1[4*q+1], acc1[4*q+2], acc1[4*q+3]);
    }
    g_nbr[(size_t)gr0*2]   = make_float4(pn0[0], pn0[1], pn0[2], S0);
    g_nbr[(size_t)gr0*2+1] = make_float4(m0, 0.f, 0.f, 0.f);
    g_nbr[(size_t)gr1*2]   = make_float4(pn1[0], pn1[1], pn1[2], S1);
    g_nbr[(size_t)gr1*2+1] = make_float4(m1, 0.f, 0.f, 0.f);
    g_em[gr0] = e0; g_em[gr1] = e1;
}

// ---------------------------------------------------------------------------
// Pass 2: warp = 4 consecutive points. Half-warp per point in the neighbor
// phase; channel-per-lane gather/max; ONE fc loop serves all 4 points.
// Point-branch constants folded per block; idx dtype probed per block.
// ---------------------------------------------------------------------------
__global__ void __launch_bounds__(128, 4) pass2_kernel(
    const float* __restrict__ feats, const void* __restrict__ idx_raw,
    const float* __restrict__ fcW, float* __restrict__ out,
    const float* __restrict__ point_W, const float* __restrict__ point_bn,
    const float* __restrict__ eta_bn,  const float* __restrict__ mu_bn,
    const float* __restrict__ map_W,   const float* __restrict__ map_bn)
{
    __shared__ __align__(16) float4 sfc[CH32*32];   // fc_W (32x128) = 16 KB
    __shared__ float sw0[CH8], stp[CH8], smw[CH8];
    __shared__ float sPA[3*CH8], sPB[3*CH8];
    __shared__ float sK0;
    __shared__ int   sIs32;

    int tid = threadIdx.x;
    const float4* fsrc = (const float4*)fcW;
    #pragma unroll
    for (int i = 0; i < 8; i++) sfc[tid + 128*i] = fsrc[tid + 128*i];

    // per-block fold + dtype probe (warp 0)
    if (tid < 32) {
        const long long* idx64 = (const long long*)idx_raw;
        long long v = idx64[tid];
        unsigned bad = __ballot_sync(0xffffffffu, v < 0 || v >= NPTS);
        float s_map = map_bn[0] * rsqrtf(map_bn[3] + EPSF);
        if (tid < CH8) {
            int c = tid;
            float sp = point_bn[0*CH8+c] * rsqrtf(point_bn[3*CH8+c] + EPSF);
            stp[c] = point_bn[1*CH8+c] - point_bn[2*CH8+c] * sp;
            sw0[c] = point_W[0*CH8+c] * sp;
            #pragma unroll
            for (int i = 0; i < 3; i++) {
                sPA[i*CH8+c] = (point_W[(1+i)*CH8+c] + point_W[(7+i)*CH8+c]) * sp;
                sPB[i*CH8+c] = (point_W[(4+i)*CH8+c] - point_W[(7+i)*CH8+c]) * sp;
            }
            smw[c] = map_W[c] * s_map;
        }
        if (tid == 0) {
            sIs32 = bad ? 1 : 0;
            float k0 = map_bn[1] - map_bn[2] * s_map;
            for (int c = 0; c < CH8; c++) {
                float se  = eta_bn[0*CH8+c] * rsqrtf(eta_bn[3*CH8+c] + EPSF);
                float te  = eta_bn[1*CH8+c] - eta_bn[2*CH8+c] * se;
                float smu = mu_bn [0*CH8+c] * rsqrtf(mu_bn [3*CH8+c] + EPSF);
                float tmu = mu_bn [1*CH8+c] - mu_bn [2*CH8+c] * smu;
                k0 += te  * map_W[1*CH8+c] * s_map;
                k0 += tmu * map_W[2*CH8+c] * s_map;
            }
            sK0 = k0;
        }
    }
    __syncthreads();

    const int is32 = sIs32;
    const int*       idx32 = (const int*)idx_raw;
    const long long* idx64 = (const long long*)idx_raw;

    // hoist folded constants into registers
    float w0r[CH8], PB0[CH8], PB1[CH8], PB2[CH8], mwr[CH8];
    float tpr[CH8], PA0[CH8], PA1[CH8], PA2[CH8];
    #pragma unroll
    for (int c = 0; c < CH8; c++) {
        w0r[c] = sw0[c];  mwr[c] = smw[c]; tpr[c] = stp[c];
        PA0[c] = sPA[0*CH8+c]; PA1[c] = sPA[1*CH8+c]; PA2[c] = sPA[2*CH8+c];
        PB0[c] = sPB[0*CH8+c]; PB1[c] = sPB[1*CH8+c]; PB2[c] = sPB[2*CH8+c];
    }
    const float K0 = sK0;

    int lane = tid & 31;
    int l16  = lane & 15;
    int half = lane >> 4;                           // 0 or 1
    int p0   = (blockIdx.x * 4 + (tid >> 5)) * 4;   // 4 points per warp

    float m[4];

    #pragma unroll
    for (int pair = 0; pair < 2; pair++) {
        int pMine = p0 + pair*2 + half;         // this lane's point
        int bbase = pMine & ~(NPTS - 1);        // b * N

        const float* fp = feats + (size_t)pMine * DIM;
        float px = __ldg(fp), py = __ldg(fp+1), pz = __ldg(fp+2);
        float Sp = px*px + py*py + pz*pz;
        float em = g_em[pMine];

        // neighbor index + per-neighbor compute (all 32 lanes active)
        size_t off = (size_t)pMine * KNN + l16;
        int jv = is32 ? idx32[off] : (int)idx64[off];
        int j = bbase + jv;
        // packed 32B record: float4 {x,y,z,S} + mm in same 128B line
        const float4* rec = (const float4*)((const char*)g_nbr + ((size_t)(unsigned)j << 5));
        float4 a = rec[0];
        float mm = rec[1].x;
        float t = Sp + a.w - 2.f * (px*a.x + py*a.y + pz*a.z);   // |p-pn|^2
        float pt = 0.f;
        #pragma unroll
        for (int c = 0; c < CH8; c++) {
            float h = tpr[c];
            h = fmaf(px, PA0[c], h);
            h = fmaf(py, PA1[c], h);
            h = fmaf(pz, PA2[c], h);
            h = fmaf(w0r[c], t, h);
            h = fmaf(a.x, PB0[c], h);
            h = fmaf(a.y, PB1[c], h);
            h = fmaf(a.z, PB2[c], h);
            h = fmaxf(h, 0.f);                 // relu(point bn)
            pt = fmaf(h, mwr[c], pt);
        }
        float g = fmaxf(pt + em + mm + K0, 0.f);   // relu(map bn)

        // channel-per-lane max over 16 neighbors, both points of the pair
        float mA = -3.402823466e38f, mB = -3.402823466e38f;
        #pragma unroll
        for (int k = 0; k < KNN; k++) {
            int   jA = __shfl_sync(0xffffffffu, j, k);
            float gA = __shfl_sync(0xffffffffu, g, k);
            int   jB = __shfl_sync(0xffffffffu, j, k + 16);
            float gB = __shfl_sync(0xffffffffu, g, k + 16);
            float vA = *(const float*)((const char*)g_gam + (((size_t)(unsigned)jA << 7) + ((unsigned)lane << 2)));
            float vB = *(const float*)((const char*)g_gam + (((size_t)(unsigned)jB << 7) + ((unsigned)lane << 2)));
            mA = fmaxf(mA, gA * vA);
            mB = fmaxf(mB, gB * vB);
        }
        m[pair*2]     = mA;
        m[pair*2 + 1] = mB;
    }

    // fc for all 4 points: out[128] = m[32] @ fc_W(32,128); 4 outs/lane/point
    float4 acc0 = make_float4(0.f,0.f,0.f,0.f);
    float4 acc1 = acc0, acc2 = acc0, acc3 = acc0;
    #pragma unroll
    for (int c = 0; c < CH32; c++) {
        float4 w = sfc[c*32 + lane];
        float m0 = __shfl_sync(0xffffffffu, m[0], c);
        float m1 = __shfl_sync(0xffffffffu, m[1], c);
        float m2 = __shfl_sync(0xffffffffu, m[2], c);
        float m3 = __shfl_sync(0xffffffffu, m[3], c);
        acc0.x = fmaf(m0, w.x, acc0.x); acc0.y = fmaf(m0, w.y, acc0.y);
        acc0.z = fmaf(m0, w.z, acc0.z); acc0.w = fmaf(m0, w.w, acc0.w);
        acc1.x = fmaf(m1, w.x, acc1.x); acc1.y = fmaf(m1, w.y, acc1.y);
        acc1.z = fmaf(m1, w.z, acc1.z); acc1.w = fmaf(m1, w.w, acc1.w);
        acc2.x = fmaf(m2, w.x, acc2.x); acc2.y = fmaf(m2, w.y, acc2.y);
        acc2.z = fmaf(m2, w.z, acc2.z); acc2.w = fmaf(m2, w.w, acc2.w);
        acc3.x = fmaf(m3, w.x, acc3.x); acc3.y = fmaf(m3, w.y, acc3.y);
        acc3.z = fmaf(m3, w.z, acc3.z); acc3.w = fmaf(m3, w.w, acc3.w);
    }
    float4* op = (float4*)out + (size_t)p0 * 32 + lane;
    op[0]  = acc0;
    op[32] = acc1;
    op[64] = acc2;
    op[96] = acc3;
}

extern "C" void kernel_launch(void* const* d_in, const int* in_sizes, int n_in,
                              void* d_out, int out_size)
{
    const float* feats    = (const float*)d_in[0];
    const void*  idx_raw  = (const void*)d_in[1];
    const float* point_W  = (const float*)d_in[2];
    const float* point_bn = (const float*)d_in[3];
    const float* eta_W    = (const float*)d_in[4];
    const float* eta_bn   = (const float*)d_in[5];
    const float* mu_W     = (const float*)d_in[6];
    const float* mu_bn    = (const float*)d_in[7];
    const float* gamma_W  = (const float*)d_in[8];
    const float* gamma_bn = (const float*)d_in[9];
    const float* map_W    = (const float*)d_in[10];
    const float* map_bn   = (const float*)d_in[11];
    const float* fc_W     = (const float*)d_in[12];
    float* out = (float*)d_out;

    pass1_kernel<<<ROWS/256, 128>>>(feats, eta_W, eta_bn, mu_W, mu_bn,
                                    gamma_W, gamma_bn, map_W, map_bn);
    // 4 points/warp * 4 warps/block = 16 points/block
    pass2_kernel<<<ROWS/16, 128>>>(feats, idx_raw, fc_W, out,
                                   point_W, point_bn, eta_bn, mu_bn,
                                   map_W, map_bn);
}

// round 5
// speedup vs baseline: 1.5806x; 1.1596x over previous
#include <cuda_runtime.h>

#define NPTS   65536
#define BATCH  2
#define ROWS   (BATCH*NPTS)
#define DIM    35
#define KNN    16
#define CH8    8
#define CH32   32
#define OUTCH  128
#define EPSF   1e-5f

// Pass-1 outputs
__device__ __align__(16) float  g_gam[(size_t)ROWS*CH32];  // 16.8 MB, L2-resident
__device__ __align__(16) float4 g_nbr[ROWS];               // {pn.x,pn.y,pn.z,mm} 16B/row
// center record: {base[0..3]},{base[4..7]},{px,py,pz,Sp},{em+K0,0,0,0} = 64B/row
__device__ __align__(16) float4 g_ctr[(size_t)ROWS*4];

// ---------------------------------------------------------------------------
// Pass 1: per-row precompute — gam[32], base[8], em', mm, pn, |pn|^2.
// ---------------------------------------------------------------------------
__global__ void __launch_bounds__(128) pass1_kernel(
    const float* __restrict__ feats,
    const float* __restrict__ point_W, const float* __restrict__ point_bn,
    const float* __restrict__ eta_W,   const float* __restrict__ eta_bn,
    const float* __restrict__ mu_W,    const float* __restrict__ mu_bn,
    const float* __restrict__ gamma_W, const float* __restrict__ gamma_bn,
    const float* __restrict__ map_W,   const float* __restrict__ map_bn)
{
    __shared__ __align__(16) float srow[256*DIM + 1];
    __shared__ float sW[DIM*CH32];
    __shared__ float stg[CH32], su[32], sv[32];
    __shared__ float sPA[3*CH8], stp[CH8];
    __shared__ float sK0;
    int tid = threadIdx.x;
    int R0  = blockIdx.x * 256;

    // stage 256 input rows coalesced
    const float4* src = (const float4*)feats + ((size_t)R0 * DIM >> 2);
    float4* dst = (float4*)srow;
    for (int i = tid; i < 256*DIM/4; i += 128) dst[i] = src[i];

    // per-block constant folding
    float s_map = map_bn[0] * rsqrtf(map_bn[3] + EPSF);
    for (int i = tid; i < DIM*CH32; i += 128) {
        int c = i & 31;
        float sg = gamma_bn[0*CH32+c] * rsqrtf(gamma_bn[3*CH32+c] + EPSF);
        sW[i] = gamma_W[i] * sg;
    }
    if (tid < CH32) {
        int c = tid;
        float sg = gamma_bn[0*CH32+c] * rsqrtf(gamma_bn[3*CH32+c] + EPSF);
        stg[c] = gamma_bn[1*CH32+c] - gamma_bn[2*CH32+c] * sg;
    }
    if (tid >= 32 && tid < 64) {
        int i = tid - 32;
        float suv = 0.f, svv = 0.f;
        for (int c = 0; c < CH8; c++) {
            float se  = eta_bn[0*CH8+c] * rsqrtf(eta_bn[3*CH8+c] + EPSF);
            float smu = mu_bn [0*CH8+c] * rsqrtf(mu_bn [3*CH8+c] + EPSF);
            suv += eta_W[i*CH8+c] * se  * (map_W[1*CH8+c] * s_map);
            svv += mu_W [i*CH8+c] * smu * (map_W[2*CH8+c] * s_map);
        }
        su[i] = suv;
        sv[i] = svv;
    }
    if (tid >= 64 && tid < 64+CH8) {
        int c = tid - 64;
        float sp = point_bn[0*CH8+c] * rsqrtf(point_bn[3*CH8+c] + EPSF);
        stp[c] = point_bn[1*CH8+c] - point_bn[2*CH8+c] * sp;
        #pragma unroll
        for (int i = 0; i < 3; i++)
            sPA[i*CH8+c] = (point_W[(1+i)*CH8+c] + point_W[(7+i)*CH8+c]) * sp;
    }
    if (tid == 96) {
        float k0 = map_bn[1] - map_bn[2] * s_map;
        for (int c = 0; c < CH8; c++) {
            float se  = eta_bn[0*CH8+c] * rsqrtf(eta_bn[3*CH8+c] + EPSF);
            float te  = eta_bn[1*CH8+c] - eta_bn[2*CH8+c] * se;
            float smu = mu_bn [0*CH8+c] * rsqrtf(mu_bn [3*CH8+c] + EPSF);
            float tmu = mu_bn [1*CH8+c] - mu_bn [2*CH8+c] * smu;
            k0 += te  * map_W[1*CH8+c] * s_map;
            k0 += tmu * map_W[2*CH8+c] * s_map;
        }
        sK0 = k0;
    }
    __syncthreads();

    float acc0[CH32], acc1[CH32];
    #pragma unroll
    for (int c = 0; c < CH32; c++) { acc0[c] = stg[c]; acc1[c] = stg[c]; }

    const float* r0 = &srow[tid * DIM];
    const float* r1 = &srow[(tid + 128) * DIM];
    float pn0[3], pn1[3];
    float S0 = 0.f, S1 = 0.f, e0 = 0.f, e1 = 0.f, m0 = 0.f, m1 = 0.f;

    #pragma unroll
    for (int d = 0; d < 3; d++) {
        float f0 = r0[d], f1 = r1[d];
        pn0[d] = f0; pn1[d] = f1;
        S0 = fmaf(f0, f0, S0); S1 = fmaf(f1, f1, S1);
        #pragma unroll
        for (int c = 0; c < CH32; c++) {
            float w = sW[d*CH32 + c];
            acc0[c] = fmaf(f0, w, acc0[c]);
            acc1[c] = fmaf(f1, w, acc1[c]);
        }
    }
    for (int d = 3; d < DIM; d++) {
        float f0 = r0[d], f1 = r1[d];
        float uu = su[d-3], vw = sv[d-3];
        e0 = fmaf(f0, uu, e0); e1 = fmaf(f1, uu, e1);
        m0 = fmaf(f0, vw, m0); m1 = fmaf(f1, vw, m1);
        #pragma unroll
        for (int c = 0; c < CH32; c++) {
            float w = sW[d*CH32 + c];
            acc0[c] = fmaf(f0, w, acc0[c]);
            acc1[c] = fmaf(f1, w, acc1[c]);
        }
    }

    // base[c] = tp[c] + p.PA  (center-row precompute)
    float b0[CH8], b1[CH8];
    #pragma unroll
    for (int c = 0; c < CH8; c++) {
        float h0 = stp[c], h1 = stp[c];
        h0 = fmaf(pn0[0], sPA[0*CH8+c], h0); h1 = fmaf(pn1[0], sPA[0*CH8+c], h1);
        h0 = fmaf(pn0[1], sPA[1*CH8+c], h0); h1 = fmaf(pn1[1], sPA[1*CH8+c], h1);
        h0 = fmaf(pn0[2], sPA[2*CH8+c], h0); h1 = fmaf(pn1[2], sPA[2*CH8+c], h1);
        b0[c] = h0; b1[c] = h1;
    }

    int gr0 = R0 + tid, gr1 = R0 + tid + 128;
    float4* gp0 = (float4*)&g_gam[(size_t)gr0 * CH32];
    float4* gp1 = (float4*)&g_gam[(size_t)gr1 * CH32];
    #pragma unroll
    for (int q = 0; q < 8; q++) {
        gp0[q] = make_float4(acc0[4*q], acc0[4*q+1], acc0[4*q+2], acc0[4*q+3]);
        gp1[q] = make_float4(acc1[4*q], acc1[4*q+1], acc1[4*q+2], acc1[4*q+3]);
    }
    g_nbr[gr0] = make_float4(pn0[0], pn0[1], pn0[2], m0);
    g_nbr[gr1] = make_float4(pn1[0], pn1[1], pn1[2], m1);
    float K0 = sK0;
    float4* cp0 = &g_ctr[(size_t)gr0*4];
    float4* cp1 = &g_ctr[(size_t)gr1*4];
    cp0[0] = make_float4(b0[0], b0[1], b0[2], b0[3]);
    cp0[1] = make_float4(b0[4], b0[5], b0[6], b0[7]);
    cp0[2] = make_float4(pn0[0], pn0[1], pn0[2], S0);
    cp0[3] = make_float4(e0 + K0, 0.f, 0.f, 0.f);
    cp1[0] = make_float4(b1[0], b1[1], b1[2], b1[3]);
    cp1[1] = make_float4(b1[4], b1[5], b1[6], b1[7]);
    cp1[2] = make_float4(pn1[0], pn1[1], pn1[2], S1);
    cp1[3] = make_float4(e1 + K0, 0.f, 0.f, 0.f);
}

// ---------------------------------------------------------------------------
// Pass 2: warp = 8 consecutive points (4 half-warp pair phases), then ONE fc
// loop for all 8 points. Single 16B gather per neighbor; center data from the
// precomputed 64B record (broadcast loads).
// ---------------------------------------------------------------------------
__global__ void __launch_bounds__(128, 4) pass2_kernel(
    const void* __restrict__ idx_raw,
    const float* __restrict__ fcW, float* __restrict__ out,
    const float* __restrict__ point_W, const float* __restrict__ point_bn,
    const float* __restrict__ map_W,   const float* __restrict__ map_bn)
{
    __shared__ __align__(16) float4 sfc[CH32*32];   // fc_W (32x128) = 16 KB
    __shared__ float sw0[CH8], smw[CH8], sPB[3*CH8];
    __shared__ int   sIs32;

    int tid = threadIdx.x;
    const float4* fsrc = (const float4*)fcW;
    #pragma unroll
    for (int i = 0; i < 8; i++) sfc[tid + 128*i] = fsrc[tid + 128*i];

    if (tid < 32) {
        const long long* i64 = (const long long*)idx_raw;
        long long v = i64[tid];
        unsigned bad = __ballot_sync(0xffffffffu, v < 0 || v >= NPTS);
        if (tid == 0) sIs32 = bad ? 1 : 0;
        float s_map = map_bn[0] * rsqrtf(map_bn[3] + EPSF);
        if (tid < CH8) {
            int c = tid;
            float sp = point_bn[0*CH8+c] * rsqrtf(point_bn[3*CH8+c] + EPSF);
            sw0[c] = point_W[0*CH8+c] * sp;
            #pragma unroll
            for (int i = 0; i < 3; i++)
                sPB[i*CH8+c] = (point_W[(4+i)*CH8+c] - point_W[(7+i)*CH8+c]) * sp;
            smw[c] = map_W[c] * s_map;
        }
    }
    __syncthreads();

    const int is32 = sIs32;
    const int*       idx32 = (const int*)idx_raw;
    const long long* idx64 = (const long long*)idx_raw;

    float w0r[CH8], PB0[CH8], PB1[CH8], PB2[CH8], mwr[CH8];
    #pragma unroll
    for (int c = 0; c < CH8; c++) {
        w0r[c] = sw0[c];  mwr[c] = smw[c];
        PB0[c] = sPB[0*CH8+c]; PB1[c] = sPB[1*CH8+c]; PB2[c] = sPB[2*CH8+c];
    }

    int lane = tid & 31;
    int l16  = lane & 15;
    int half = lane >> 4;                           // 0 or 1
    int p0   = (blockIdx.x * 4 + (tid >> 5)) * 8;   // 8 points per warp

    float m[8];

    #pragma unroll
    for (int pair = 0; pair < 4; pair++) {
        int pMine = p0 + pair*2 + half;
        int bbase = pMine & ~(NPTS - 1);            // b * N

        // center record (broadcast within half-warp)
        const float4* cp = &g_ctr[(size_t)pMine*4];
        float4 cb0 = cp[0];
        float4 cb1 = cp[1];
        float4 cpp = cp[2];                          // {px,py,pz,Sp}
        float  em  = cp[3].x;                        // em + K0
        float base[CH8] = {cb0.x, cb0.y, cb0.z, cb0.w, cb1.x, cb1.y, cb1.z, cb1.w};

        // neighbor index + single 16B gather
        size_t off = (size_t)pMine * KNN + l16;
        int jv = is32 ? idx32[off] : (int)idx64[off];
        int j = bbase + jv;
        float4 a = *(const float4*)((const char*)g_nbr + ((size_t)(unsigned)j << 4));
        // |pn|^2 recomputed (fma headroom), mm rides in a.w
        float Sj = fmaf(a.x, a.x, fmaf(a.y, a.y, a.z*a.z));
        float t  = cpp.w + Sj - 2.f * (cpp.x*a.x + cpp.y*a.y + cpp.z*a.z);
        float pt = 0.f;
        #pragma unroll
        for (int c = 0; c < CH8; c++) {
            float h = base[c];
            h = fmaf(w0r[c], t, h);
            h = fmaf(a.x, PB0[c], h);
            h = fmaf(a.y, PB1[c], h);
            h = fmaf(a.z, PB2[c], h);
            h = fmaxf(h, 0.f);                      // relu(point bn)
            pt = fmaf(h, mwr[c], pt);
        }
        float g = fmaxf(pt + em + a.w, 0.f);        // relu(map bn)

        // channel-per-lane max over 16 neighbors, both points of the pair
        float mA = -3.402823466e38f, mB = -3.402823466e38f;
        #pragma unroll
        for (int k = 0; k < KNN; k++) {
            int   jA = __shfl_sync(0xffffffffu, j, k);
            float gA = __shfl_sync(0xffffffffu, g, k);
            int   jB = __shfl_sync(0xffffffffu, j, k + 16);
            float gB = __shfl_sync(0xffffffffu, g, k + 16);
            float vA = *(const float*)((const char*)g_gam + (((size_t)(unsigned)jA << 7) + ((unsigned)lane << 2)));
            float vB = *(const float*)((const char*)g_gam + (((size_t)(unsigned)jB << 7) + ((unsigned)lane << 2)));
            mA = fmaxf(mA, gA * vA);
            mB = fmaxf(mB, gB * vB);
        }
        m[pair*2]     = mA;
        m[pair*2 + 1] = mB;
    }

    // fc for 8 points: out[128] = m[32] @ fc_W(32,128); 4 outs/lane/point
    float4 acc[8];
    #pragma unroll
    for (int i = 0; i < 8; i++) acc[i] = make_float4(0.f, 0.f, 0.f, 0.f);
    #pragma unroll
    for (int c = 0; c < CH32; c++) {
        float4 w = sfc[c*32 + lane];
        #pragma unroll
        for (int i = 0; i < 8; i++) {
            float mc = __shfl_sync(0xffffffffu, m[i], c);
            acc[i].x = fmaf(mc, w.x, acc[i].x);
            acc[i].y = fmaf(mc, w.y, acc[i].y);
            acc[i].z = fmaf(mc, w.z, acc[i].z);
            acc[i].w = fmaf(mc, w.w, acc[i].w);
        }
    }
    float4* op = (float4*)out + (size_t)p0 * 32 + lane;
    #pragma unroll
    for (int i = 0; i < 8; i++) op[i*32] = acc[i];
}

extern "C" void kernel_launch(void* const* d_in, const int* in_sizes, int n_in,
                              void* d_out, int out_size)
{
    const float* feats    = (const float*)d_in[0];
    const void*  idx_raw  = (const void*)d_in[1];
    const float* point_W  = (const float*)d_in[2];
    const float* point_bn = (const float*)d_in[3];
    const float* eta_W    = (const float*)d_in[4];
    const float* eta_bn   = (const float*)d_in[5];
    const float* mu_W     = (const float*)d_in[6];
    const float* mu_bn    = (const float*)d_in[7];
    const float* gamma_W  = (const float*)d_in[8];
    const float* gamma_bn = (const float*)d_in[9];
    const float* map_W    = (const float*)d_in[10];
    const float* map_bn   = (const float*)d_in[11];
    const float* fc_W     = (const float*)d_in[12];
    float* out = (float*)d_out;

    pass1_kernel<<<ROWS/256, 128>>>(feats, point_W, point_bn, eta_W, eta_bn,
                                    mu_W, mu_bn, gamma_W, gamma_bn,
                                    map_W, map_bn);
    // 8 points/warp * 4 warps/block = 32 points/block
    pass2_kernel<<<ROWS/32, 128>>>(idx_raw, fc_W, out,
                                   point_W, point_bn, map_W, map_bn);
}

// round 6
// speedup vs baseline: 1.6686x; 1.0557x over previous
#include <cuda_runtime.h>

#define NPTS   65536
#define BATCH  2
#define ROWS   (BATCH*NPTS)
#define DIM    35
#define KNN    16
#define CH8    8
#define CH32   32
#define OUTCH  128
#define EPSF   1e-5f

typedef unsigned long long u64;

// packed fp32x2 helpers (FFMA2 — ptxas never emits these from C++)
__device__ __forceinline__ u64 pk2(float lo, float hi) {
    u64 r; asm("mov.b64 %0, {%1, %2};" : "=l"(r) : "f"(lo), "f"(hi)); return r;
}
__device__ __forceinline__ void up2(u64 v, float& lo, float& hi) {
    asm("mov.b64 {%0, %1}, %2;" : "=f"(lo), "=f"(hi) : "l"(v));
}
__device__ __forceinline__ u64 ff2(u64 a, u64 b, u64 c) {
    u64 d; asm("fma.rn.f32x2 %0, %1, %2, %3;" : "=l"(d) : "l"(a), "l"(b), "l"(c)); return d;
}

// Pass-1 outputs
__device__ __align__(16) float  g_gam[(size_t)ROWS*CH32];  // 16.8 MB, L2-resident
__device__ __align__(16) float4 g_nbr[ROWS];               // {pn.x,pn.y,pn.z,mm}
// center record: {base[0..3]},{base[4..7]},{px,py,pz,Sp},{em+K0,...} = 64B/row
__device__ __align__(16) float4 g_ctr[(size_t)ROWS*4];

// ---------------------------------------------------------------------------
// Pass 1: per-row precompute — gam[32], base[8], em', mm, pn.
// ---------------------------------------------------------------------------
__global__ void __launch_bounds__(128) pass1_kernel(
    const float* __restrict__ feats,
    const float* __restrict__ point_W, const float* __restrict__ point_bn,
    const float* __restrict__ eta_W,   const float* __restrict__ eta_bn,
    const float* __restrict__ mu_W,    const float* __restrict__ mu_bn,
    const float* __restrict__ gamma_W, const float* __restrict__ gamma_bn,
    const float* __restrict__ map_W,   const float* __restrict__ map_bn)
{
    __shared__ __align__(16) float srow[256*DIM + 1];
    __shared__ __align__(16) float sW[DIM*CH32];
    __shared__ __align__(16) float stg[CH32];
    __shared__ __align__(16) float sPA[3*CH8], stp[CH8];
    __shared__ float su[32], sv[32];
    __shared__ float sK0;
    int tid = threadIdx.x;
    int R0  = blockIdx.x * 256;

    // stage 256 input rows coalesced
    const float4* src = (const float4*)feats + ((size_t)R0 * DIM >> 2);
    float4* dst = (float4*)srow;
    for (int i = tid; i < 256*DIM/4; i += 128) dst[i] = src[i];

    // per-block constant folding
    float s_map = map_bn[0] * rsqrtf(map_bn[3] + EPSF);
    for (int i = tid; i < DIM*CH32; i += 128) {
        int c = i & 31;
        float sg = gamma_bn[0*CH32+c] * rsqrtf(gamma_bn[3*CH32+c] + EPSF);
        sW[i] = gamma_W[i] * sg;
    }
    if (tid < CH32) {
        int c = tid;
        float sg = gamma_bn[0*CH32+c] * rsqrtf(gamma_bn[3*CH32+c] + EPSF);
        stg[c] = gamma_bn[1*CH32+c] - gamma_bn[2*CH32+c] * sg;
    }
    if (tid >= 32 && tid < 64) {
        int i = tid - 32;
        float suv = 0.f, svv = 0.f;
        for (int c = 0; c < CH8; c++) {
            float se  = eta_bn[0*CH8+c] * rsqrtf(eta_bn[3*CH8+c] + EPSF);
            float smu = mu_bn [0*CH8+c] * rsqrtf(mu_bn [3*CH8+c] + EPSF);
            suv += eta_W[i*CH8+c] * se  * (map_W[1*CH8+c] * s_map);
            svv += mu_W [i*CH8+c] * smu * (map_W[2*CH8+c] * s_map);
        }
        su[i] = suv;
        sv[i] = svv;
    }
    if (tid >= 64 && tid < 64+CH8) {
        int c = tid - 64;
        float sp = point_bn[0*CH8+c] * rsqrtf(point_bn[3*CH8+c] + EPSF);
        stp[c] = point_bn[1*CH8+c] - point_bn[2*CH8+c] * sp;
        #pragma unroll
        for (int i = 0; i < 3; i++)
            sPA[i*CH8+c] = (point_W[(1+i)*CH8+c] + point_W[(7+i)*CH8+c]) * sp;
    }
    if (tid == 96) {
        float k0 = map_bn[1] - map_bn[2] * s_map;
        for (int c = 0; c < CH8; c++) {
            float se  = eta_bn[0*CH8+c] * rsqrtf(eta_bn[3*CH8+c] + EPSF);
            float te  = eta_bn[1*CH8+c] - eta_bn[2*CH8+c] * se;
            float smu = mu_bn [0*CH8+c] * rsqrtf(mu_bn [3*CH8+c] + EPSF);
            float tmu = mu_bn [1*CH8+c] - mu_bn [2*CH8+c] * smu;
            k0 += te  * map_W[1*CH8+c] * s_map;
            k0 += tmu * map_W[2*CH8+c] * s_map;
        }
        sK0 = k0;
    }
    __syncthreads();

    // packed accumulators: 16 f32x2 per row
    u64 acc0[16], acc1[16];
    const u64* stg2 = (const u64*)stg;
    #pragma unroll
    for (int q = 0; q < 16; q++) { acc0[q] = stg2[q]; acc1[q] = stg2[q]; }

    const float* r0 = &srow[tid * DIM];
    const float* r1 = &srow[(tid + 128) * DIM];
    float pn0[3], pn1[3];
    float S0 = 0.f, S1 = 0.f, e0 = 0.f, e1 = 0.f, m0 = 0.f, m1 = 0.f;

    #pragma unroll
    for (int d = 0; d < 3; d++) {
        float f0 = r0[d], f1 = r1[d];
        pn0[d] = f0; pn1[d] = f1;
        S0 = fmaf(f0, f0, S0); S1 = fmaf(f1, f1, S1);
        u64 pf0 = pk2(f0, f0), pf1 = pk2(f1, f1);
        const u64* w2 = (const u64*)&sW[d*CH32];
        #pragma unroll
        for (int q = 0; q < 16; q++) {
            u64 w = w2[q];
            acc0[q] = ff2(pf0, w, acc0[q]);
            acc1[q] = ff2(pf1, w, acc1[q]);
        }
    }
    for (int d = 3; d < DIM; d++) {
        float f0 = r0[d], f1 = r1[d];
        float uu = su[d-3], vw = sv[d-3];
        e0 = fmaf(f0, uu, e0); e1 = fmaf(f1, uu, e1);
        m0 = fmaf(f0, vw, m0); m1 = fmaf(f1, vw, m1);
        u64 pf0 = pk2(f0, f0), pf1 = pk2(f1, f1);
        const u64* w2 = (const u64*)&sW[d*CH32];
        #pragma unroll
        for (int q = 0; q < 16; q++) {
            u64 w = w2[q];
            acc0[q] = ff2(pf0, w, acc0[q]);
            acc1[q] = ff2(pf1, w, acc1[q]);
        }
    }

    // base[c] = tp[c] + p.PA  (packed in channel pairs)
    u64 b0p[4], b1p[4];
    {
        const u64* tp2 = (const u64*)stp;
        const u64* pa0 = (const u64*)&sPA[0];
        const u64* pa1 = (const u64*)&sPA[CH8];
        const u64* pa2 = (const u64*)&sPA[2*CH8];
        u64 x0 = pk2(pn0[0], pn0[0]), y0 = pk2(pn0[1], pn0[1]), z0 = pk2(pn0[2], pn0[2]);
        u64 x1 = pk2(pn1[0], pn1[0]), y1 = pk2(pn1[1], pn1[1]), z1 = pk2(pn1[2], pn1[2]);
        #pragma unroll
        for (int q = 0; q < 4; q++) {
            u64 h0 = tp2[q], h1 = tp2[q];
            h0 = ff2(x0, pa0[q], h0); h1 = ff2(x1, pa0[q], h1);
            h0 = ff2(y0, pa1[q], h0); h1 = ff2(y1, pa1[q], h1);
            h0 = ff2(z0, pa2[q], h0); h1 = ff2(z1, pa2[q], h1);
            b0p[q] = h0; b1p[q] = h1;
        }
    }

    int gr0 = R0 + tid, gr1 = R0 + tid + 128;
    ulonglong2* gp0 = (ulonglong2*)&g_gam[(size_t)gr0 * CH32];
    ulonglong2* gp1 = (ulonglong2*)&g_gam[(size_t)gr1 * CH32];
    #pragma unroll
    for (int q = 0; q < 8; q++) {
        gp0[q] = make_ulonglong2(acc0[2*q], acc0[2*q+1]);
        gp1[q] = make_ulonglong2(acc1[2*q], acc1[2*q+1]);
    }
    g_nbr[gr0] = make_float4(pn0[0], pn0[1], pn0[2], m0);
    g_nbr[gr1] = make_float4(pn1[0], pn1[1], pn1[2], m1);
    float K0 = sK0;
    ulonglong2* cp0 = (ulonglong2*)&g_ctr[(size_t)gr0*4];
    ulonglong2* cp1 = (ulonglong2*)&g_ctr[(size_t)gr1*4];
    cp0[0] = make_ulonglong2(b0p[0], b0p[1]);
    cp0[1] = make_ulonglong2(b0p[2], b0p[3]);
    cp0[2] = make_ulonglong2(pk2(pn0[0], pn0[1]), pk2(pn0[2], S0));
    cp0[3] = make_ulonglong2(pk2(e0 + K0, 0.f), 0ull);
    cp1[0] = make_ulonglong2(b1p[0], b1p[1]);
    cp1[1] = make_ulonglong2(b1p[2], b1p[3]);
    cp1[2] = make_ulonglong2(pk2(pn1[0], pn1[1]), pk2(pn1[2], S1));
    cp1[3] = make_ulonglong2(pk2(e1 + K0, 0.f), 0ull);
}

// ---------------------------------------------------------------------------
// Pass 2: warp = 8 consecutive points (4 half-warp pair phases), then ONE fc
// loop for all 8 points using packed f32x2 FMA (two points per instruction).
// ---------------------------------------------------------------------------
__global__ void __launch_bounds__(128, 4) pass2_kernel(
    const void* __restrict__ idx_raw,
    const float* __restrict__ fcW, float* __restrict__ out,
    const float* __restrict__ point_W, const float* __restrict__ point_bn,
    const float* __restrict__ map_W,   const float* __restrict__ map_bn)
{
    __shared__ __align__(16) float4 sfc[CH32*32];   // fc_W (32x128) = 16 KB
    __shared__ __align__(16) float sw0[CH8], sPB[3*CH8];
    __shared__ float smw[CH8];
    __shared__ int   sIs32;

    int tid = threadIdx.x;
    const float4* fsrc = (const float4*)fcW;
    #pragma unroll
    for (int i = 0; i < 8; i++) sfc[tid + 128*i] = fsrc[tid + 128*i];

    if (tid < 32) {
        const long long* i64 = (const long long*)idx_raw;
        long long v = i64[tid];
        unsigned bad = __ballot_sync(0xffffffffu, v < 0 || v >= NPTS);
        if (tid == 0) sIs32 = bad ? 1 : 0;
        float s_map = map_bn[0] * rsqrtf(map_bn[3] + EPSF);
        if (tid < CH8) {
            int c = tid;
            float sp = point_bn[0*CH8+c] * rsqrtf(point_bn[3*CH8+c] + EPSF);
            sw0[c] = point_W[0*CH8+c] * sp;
            #pragma unroll
            for (int i = 0; i < 3; i++)
                sPB[i*CH8+c] = (point_W[(4+i)*CH8+c] - point_W[(7+i)*CH8+c]) * sp;
            smw[c] = map_W[c] * s_map;
        }
    }
    __syncthreads();

    const int is32 = sIs32;
    const int*       idx32 = (const int*)idx_raw;
    const long long* idx64 = (const long long*)idx_raw;

    // packed channel-pair constants
    u64 w02[4], PB0p[4], PB1p[4], PB2p[4];
    float mwr[CH8];
    {
        const u64* a = (const u64*)sw0;
        const u64* b0 = (const u64*)&sPB[0];
        const u64* b1 = (const u64*)&sPB[CH8];
        const u64* b2 = (const u64*)&sPB[2*CH8];
        #pragma unroll
        for (int q = 0; q < 4; q++) {
            w02[q] = a[q]; PB0p[q] = b0[q]; PB1p[q] = b1[q]; PB2p[q] = b2[q];
        }
        #pragma unroll
        for (int c = 0; c < CH8; c++) mwr[c] = smw[c];
    }

    int lane = tid & 31;
    int l16  = lane & 15;
    int half = lane >> 4;                           // 0 or 1
    int p0   = (blockIdx.x * 4 + (tid >> 5)) * 8;   // 8 points per warp

    float m[8];

    #pragma unroll
    for (int pair = 0; pair < 4; pair++) {
        int pMine = p0 + pair*2 + half;
        int bbase = pMine & ~(NPTS - 1);            // b * N

        // center record (broadcast within half-warp): base pairs + p + Sp + em'
        const ulonglong2* cp = (const ulonglong2*)&g_ctr[(size_t)pMine*4];
        ulonglong2 c01 = cp[0];
        ulonglong2 c23 = cp[1];
        float4 cpp = ((const float4*)cp)[2];        // {px,py,pz,Sp}
        float  em  = ((const float*)cp)[12];        // em + K0
        u64 base2[4] = {c01.x, c01.y, c23.x, c23.y};

        // neighbor index + single 16B gather
        size_t off = (size_t)pMine * KNN + l16;
        int jv = is32 ? idx32[off] : (int)idx64[off];
        int j = bbase + jv;
        float4 a = *(const float4*)((const char*)g_nbr + ((size_t)(unsigned)j << 4));
        // |pn|^2 recomputed; mm rides in a.w
        float Sj = fmaf(a.x, a.x, fmaf(a.y, a.y, a.z*a.z));
        float t  = cpp.w + Sj - 2.f * (cpp.x*a.x + cpp.y*a.y + cpp.z*a.z);

        u64 tt = pk2(t, t);
        u64 ax = pk2(a.x, a.x), ay = pk2(a.y, a.y), az = pk2(a.z, a.z);
        float pt = 0.f;
        #pragma unroll
        for (int q = 0; q < 4; q++) {
            u64 h = base2[q];
            h = ff2(w02[q],  tt, h);
            h = ff2(ax, PB0p[q], h);
            h = ff2(ay, PB1p[q], h);
            h = ff2(az, PB2p[q], h);
            float hl, hh; up2(h, hl, hh);
            pt = fmaf(fmaxf(hl, 0.f), mwr[2*q],   pt);   // relu(point bn) . mw
            pt = fmaf(fmaxf(hh, 0.f), mwr[2*q+1], pt);
        }
        float g = fmaxf(pt + em + a.w, 0.f);        // relu(map bn)

        // channel-per-lane max over 16 neighbors, both points of the pair
        float mA = -3.402823466e38f, mB = -3.402823466e38f;
        #pragma unroll
        for (int k = 0; k < KNN; k++) {
            int   jA = __shfl_sync(0xffffffffu, j, k);
            float gA = __shfl_sync(0xffffffffu, g, k);
            int   jB = __shfl_sync(0xffffffffu, j, k + 16);
            float gB = __shfl_sync(0xffffffffu, g, k + 16);
            float vA = *(const float*)((const char*)g_gam + (((size_t)(unsigned)jA << 7) + ((unsigned)lane << 2)));
            float vB = *(const float*)((const char*)g_gam + (((size_t)(unsigned)jB << 7) + ((unsigned)lane << 2)));
            mA = fmaxf(mA, gA * vA);
            mB = fmaxf(mB, gB * vB);
        }
        m[pair*2]     = mA;
        m[pair*2 + 1] = mB;
    }

    // fc for 8 points, two points packed per f32x2 lane:
    // accX[p] = {out_x(pt 2p), out_x(pt 2p+1)} etc.
    u64 accx[4], accy[4], accz[4], accw[4];
    #pragma unroll
    for (int p = 0; p < 4; p++) { accx[p] = 0; accy[p] = 0; accz[p] = 0; accw[p] = 0; }
    #pragma unroll
    for (int c = 0; c < CH32; c++) {
        float4 w = sfc[c*32 + lane];
        u64 wxx = pk2(w.x, w.x), wyy = pk2(w.y, w.y);
        u64 wzz = pk2(w.z, w.z), www = pk2(w.w, w.w);
        #pragma unroll
        for (int p = 0; p < 4; p++) {
            float mc0 = __shfl_sync(0xffffffffu, m[2*p],   c);
            float mc1 = __shfl_sync(0xffffffffu, m[2*p+1], c);
            u64 mm01 = pk2(mc0, mc1);
            accx[p] = ff2(mm01, wxx, accx[p]);
            accy[p] = ff2(mm01, wyy, accy[p]);
            accz[p] = ff2(mm01, wzz, accz[p]);
            accw[p] = ff2(mm01, www, accw[p]);
        }
    }
    float4* op = (float4*)out + (size_t)p0 * 32 + lane;
    #pragma unroll
    for (int p = 0; p < 4; p++) {
        float x0, x1, y0, y1, z0, z1, w0, w1;
        up2(accx[p], x0, x1); up2(accy[p], y0, y1);
        up2(accz[p], z0, z1); up2(accw[p], w0, w1);
        op[(2*p)*32]   = make_float4(x0, y0, z0, w0);
        op[(2*p+1)*32] = make_float4(x1, y1, z1, w1);
    }
}

extern "C" void kernel_launch(void* const* d_in, const int* in_sizes, int n_in,
                              void* d_out, int out_size)
{
    const float* feats    = (const float*)d_in[0];
    const void*  idx_raw  = (const void*)d_in[1];
    const float* point_W  = (const float*)d_in[2];
    const float* point_bn = (const float*)d_in[3];
    const float* eta_W    = (const float*)d_in[4];
    const float* eta_bn   = (const float*)d_in[5];
    const float* mu_W     = (const float*)d_in[6];
    const float* mu_bn    = (const float*)d_in[7];
    const float* gamma_W  = (const float*)d_in[8];
    const float* gamma_bn = (const float*)d_in[9];
    const float* map_W    = (const float*)d_in[10];
    const float* map_bn   = (const float*)d_in[11];
    const float* fc_W     = (const float*)d_in[12];
    float* out = (float*)d_out;

    pass1_kernel<<<ROWS/256, 128>>>(feats, point_W, point_bn, eta_W, eta_bn,
                                    mu_W, mu_bn, gamma_W, gamma_bn,
                                    map_W, map_bn);
    // 8 points/warp * 4 warps/block = 32 points/block
    pass2_kernel<<<ROWS/32, 128>>>(idx_raw, fc_W, out,
                                   point_W, point_bn, map_W, map_bn);
}

// round 7
// speedup vs baseline: 1.7410x; 1.0433x over previous
#include <cuda_runtime.h>

#define NPTS   65536
#define BATCH  2
#define ROWS   (BATCH*NPTS)
#define DIM    35
#define KNN    16
#define CH8    8
#define CH32   32
#define OUTCH  128
#define EPSF   1e-5f

typedef unsigned long long u64;

// packed fp32x2 helpers (FFMA2 — ptxas never emits these from C++)
__device__ __forceinline__ u64 pk2(float lo, float hi) {
    u64 r; asm("mov.b64 %0, {%1, %2};" : "=l"(r) : "f"(lo), "f"(hi)); return r;
}
__device__ __forceinline__ void up2(u64 v, float& lo, float& hi) {
    asm("mov.b64 {%0, %1}, %2;" : "=f"(lo), "=f"(hi) : "l"(v));
}
__device__ __forceinline__ u64 ff2(u64 a, u64 b, u64 c) {
    u64 d; asm("fma.rn.f32x2 %0, %1, %2, %3;" : "=l"(d) : "l"(a), "l"(b), "l"(c)); return d;
}

// Pass-1 outputs
__device__ __align__(16) float  g_gam[(size_t)ROWS*CH32];  // 16.8 MB, L2-resident
__device__ __align__(16) float4 g_nbr[ROWS];               // {pn.x,pn.y,pn.z,mm}
// center record: {base[0..3]},{base[4..7]},{px,py,pz,Sp},{em+K0,...} = 64B/row
__device__ __align__(16) float4 g_ctr[(size_t)ROWS*4];

// ---------------------------------------------------------------------------
// Pass 1: per-row precompute — gam[32], base[8], em', mm, pn.
// ---------------------------------------------------------------------------
__global__ void __launch_bounds__(128) pass1_kernel(
    const float* __restrict__ feats,
    const float* __restrict__ point_W, const float* __restrict__ point_bn,
    const float* __restrict__ eta_W,   const float* __restrict__ eta_bn,
    const float* __restrict__ mu_W,    const float* __restrict__ mu_bn,
    const float* __restrict__ gamma_W, const float* __restrict__ gamma_bn,
    const float* __restrict__ map_W,   const float* __restrict__ map_bn)
{
    __shared__ __align__(16) float srow[256*DIM + 1];
    __shared__ __align__(16) float sW[DIM*CH32];
    __shared__ __align__(16) float stg[CH32];
    __shared__ __align__(16) float sPA[3*CH8], stp[CH8];
    __shared__ float su[32], sv[32];
    __shared__ float sK0;
    int tid = threadIdx.x;
    int R0  = blockIdx.x * 256;

    // stage 256 input rows coalesced
    const float4* src = (const float4*)feats + ((size_t)R0 * DIM >> 2);
    float4* dst = (float4*)srow;
    for (int i = tid; i < 256*DIM/4; i += 128) dst[i] = src[i];

    // per-block constant folding
    float s_map = map_bn[0] * rsqrtf(map_bn[3] + EPSF);
    for (int i = tid; i < DIM*CH32; i += 128) {
        int c = i & 31;
        float sg = gamma_bn[0*CH32+c] * rsqrtf(gamma_bn[3*CH32+c] + EPSF);
        sW[i] = gamma_W[i] * sg;
    }
    if (tid < CH32) {
        int c = tid;
        float sg = gamma_bn[0*CH32+c] * rsqrtf(gamma_bn[3*CH32+c] + EPSF);
        stg[c] = gamma_bn[1*CH32+c] - gamma_bn[2*CH32+c] * sg;
    }
    if (tid >= 32 && tid < 64) {
        int i = tid - 32;
        float suv = 0.f, svv = 0.f;
        for (int c = 0; c < CH8; c++) {
            float se  = eta_bn[0*CH8+c] * rsqrtf(eta_bn[3*CH8+c] + EPSF);
            float smu = mu_bn [0*CH8+c] * rsqrtf(mu_bn [3*CH8+c] + EPSF);
            suv += eta_W[i*CH8+c] * se  * (map_W[1*CH8+c] * s_map);
            svv += mu_W [i*CH8+c] * smu * (map_W[2*CH8+c] * s_map);
        }
        su[i] = suv;
        sv[i] = svv;
    }
    if (tid >= 64 && tid < 64+CH8) {
        int c = tid - 64;
        float sp = point_bn[0*CH8+c] * rsqrtf(point_bn[3*CH8+c] + EPSF);
        stp[c] = point_bn[1*CH8+c] - point_bn[2*CH8+c] * sp;
        #pragma unroll
        for (int i = 0; i < 3; i++)
            sPA[i*CH8+c] = (point_W[(1+i)*CH8+c] + point_W[(7+i)*CH8+c]) * sp;
    }
    if (tid == 96) {
        float k0 = map_bn[1] - map_bn[2] * s_map;
        for (int c = 0; c < CH8; c++) {
            float se  = eta_bn[0*CH8+c] * rsqrtf(eta_bn[3*CH8+c] + EPSF);
            float te  = eta_bn[1*CH8+c] - eta_bn[2*CH8+c] * se;
            float smu = mu_bn [0*CH8+c] * rsqrtf(mu_bn [3*CH8+c] + EPSF);
            float tmu = mu_bn [1*CH8+c] - mu_bn [2*CH8+c] * smu;
            k0 += te  * map_W[1*CH8+c] * s_map;
            k0 += tmu * map_W[2*CH8+c] * s_map;
        }
        sK0 = k0;
    }
    __syncthreads();

    // packed accumulators: 16 f32x2 per row
    u64 acc0[16], acc1[16];
    const u64* stg2 = (const u64*)stg;
    #pragma unroll
    for (int q = 0; q < 16; q++) { acc0[q] = stg2[q]; acc1[q] = stg2[q]; }

    const float* r0 = &srow[tid * DIM];
    const float* r1 = &srow[(tid + 128) * DIM];
    float pn0[3], pn1[3];
    float S0 = 0.f, S1 = 0.f, e0 = 0.f, e1 = 0.f, m0 = 0.f, m1 = 0.f;

    #pragma unroll
    for (int d = 0; d < 3; d++) {
        float f0 = r0[d], f1 = r1[d];
        pn0[d] = f0; pn1[d] = f1;
        S0 = fmaf(f0, f0, S0); S1 = fmaf(f1, f1, S1);
        u64 pf0 = pk2(f0, f0), pf1 = pk2(f1, f1);
        const u64* w2 = (const u64*)&sW[d*CH32];
        #pragma unroll
        for (int q = 0; q < 16; q++) {
            u64 w = w2[q];
            acc0[q] = ff2(pf0, w, acc0[q]);
            acc1[q] = ff2(pf1, w, acc1[q]);
        }
    }
    for (int d = 3; d < DIM; d++) {
        float f0 = r0[d], f1 = r1[d];
        float uu = su[d-3], vw = sv[d-3];
        e0 = fmaf(f0, uu, e0); e1 = fmaf(f1, uu, e1);
        m0 = fmaf(f0, vw, m0); m1 = fmaf(f1, vw, m1);
        u64 pf0 = pk2(f0, f0), pf1 = pk2(f1, f1);
        const u64* w2 = (const u64*)&sW[d*CH32];
        #pragma unroll
        for (int q = 0; q < 16; q++) {
            u64 w = w2[q];
            acc0[q] = ff2(pf0, w, acc0[q]);
            acc1[q] = ff2(pf1, w, acc1[q]);
        }
    }

    // base[c] = tp[c] + p.PA  (packed in channel pairs)
    u64 b0p[4], b1p[4];
    {
        const u64* tp2 = (const u64*)stp;
        const u64* pa0 = (const u64*)&sPA[0];
        const u64* pa1 = (const u64*)&sPA[CH8];
        const u64* pa2 = (const u64*)&sPA[2*CH8];
        u64 x0 = pk2(pn0[0], pn0[0]), y0 = pk2(pn0[1], pn0[1]), z0 = pk2(pn0[2], pn0[2]);
        u64 x1 = pk2(pn1[0], pn1[0]), y1 = pk2(pn1[1], pn1[1]), z1 = pk2(pn1[2], pn1[2]);
        #pragma unroll
        for (int q = 0; q < 4; q++) {
            u64 h0 = tp2[q], h1 = tp2[q];
            h0 = ff2(x0, pa0[q], h0); h1 = ff2(x1, pa0[q], h1);
            h0 = ff2(y0, pa1[q], h0); h1 = ff2(y1, pa1[q], h1);
            h0 = ff2(z0, pa2[q], h0); h1 = ff2(z1, pa2[q], h1);
            b0p[q] = h0; b1p[q] = h1;
        }
    }

    int gr0 = R0 + tid, gr1 = R0 + tid + 128;
    ulonglong2* gp0 = (ulonglong2*)&g_gam[(size_t)gr0 * CH32];
    ulonglong2* gp1 = (ulonglong2*)&g_gam[(size_t)gr1 * CH32];
    #pragma unroll
    for (int q = 0; q < 8; q++) {
        gp0[q] = make_ulonglong2(acc0[2*q], acc0[2*q+1]);
        gp1[q] = make_ulonglong2(acc1[2*q], acc1[2*q+1]);
    }
    g_nbr[gr0] = make_float4(pn0[0], pn0[1], pn0[2], m0);
    g_nbr[gr1] = make_float4(pn1[0], pn1[1], pn1[2], m1);
    float K0 = sK0;
    ulonglong2* cp0 = (ulonglong2*)&g_ctr[(size_t)gr0*4];
    ulonglong2* cp1 = (ulonglong2*)&g_ctr[(size_t)gr1*4];
    cp0[0] = make_ulonglong2(b0p[0], b0p[1]);
    cp0[1] = make_ulonglong2(b0p[2], b0p[3]);
    cp0[2] = make_ulonglong2(pk2(pn0[0], pn0[1]), pk2(pn0[2], S0));
    cp0[3] = make_ulonglong2(pk2(e0 + K0, 0.f), 0ull);
    cp1[0] = make_ulonglong2(b1p[0], b1p[1]);
    cp1[1] = make_ulonglong2(b1p[2], b1p[3]);
    cp1[2] = make_ulonglong2(pk2(pn1[0], pn1[1]), pk2(pn1[2], S1));
    cp1[3] = make_ulonglong2(pk2(e1 + K0, 0.f), 0ull);
}

// ---------------------------------------------------------------------------
// Pass 2: warp = 8 consecutive points. Shuffle-free: per-warp smem staging of
// (j,g) pairs and of the m matrix; fc reads m via broadcast LDS.128.
// ---------------------------------------------------------------------------
__global__ void __launch_bounds__(128, 5) pass2_kernel(
    const void* __restrict__ idx_raw,
    const float* __restrict__ fcW, float* __restrict__ out,
    const float* __restrict__ point_W, const float* __restrict__ point_bn,
    const float* __restrict__ map_W,   const float* __restrict__ map_bn)
{
    __shared__ __align__(16) float4 sfc[CH32*32];     // fc_W (32x128) = 16 KB
    __shared__ __align__(16) float  sm[4][32][8];     // m matrix, 4 KB
    __shared__ __align__(8)  uint2  sjg[4][4][32];    // (j,g) per phase, 4 KB
    __shared__ __align__(16) float  sw0[CH8], sPB[3*CH8];
    __shared__ float smw[CH8];
    __shared__ int   sIs32;

    int tid = threadIdx.x;
    const float4* fsrc = (const float4*)fcW;
    #pragma unroll
    for (int i = 0; i < 8; i++) sfc[tid + 128*i] = fsrc[tid + 128*i];

    if (tid < 32) {
        const long long* i64 = (const long long*)idx_raw;
        long long v = i64[tid];
        unsigned bad = __ballot_sync(0xffffffffu, v < 0 || v >= NPTS);
        if (tid == 0) sIs32 = bad ? 1 : 0;
        float s_map = map_bn[0] * rsqrtf(map_bn[3] + EPSF);
        if (tid < CH8) {
            int c = tid;
            float sp = point_bn[0*CH8+c] * rsqrtf(point_bn[3*CH8+c] + EPSF);
            sw0[c] = point_W[0*CH8+c] * sp;
            #pragma unroll
            for (int i = 0; i < 3; i++)
                sPB[i*CH8+c] = (point_W[(4+i)*CH8+c] - point_W[(7+i)*CH8+c]) * sp;
            smw[c] = map_W[c] * s_map;
        }
    }
    __syncthreads();

    const int is32 = sIs32;
    const int*       idx32 = (const int*)idx_raw;
    const long long* idx64 = (const long long*)idx_raw;

    // packed channel-pair constants
    u64 w02[4], PB0p[4], PB1p[4], PB2p[4];
    float mwr[CH8];
    {
        const u64* a  = (const u64*)sw0;
        const u64* b0 = (const u64*)&sPB[0];
        const u64* b1 = (const u64*)&sPB[CH8];
        const u64* b2 = (const u64*)&sPB[2*CH8];
        #pragma unroll
        for (int q = 0; q < 4; q++) {
            w02[q] = a[q]; PB0p[q] = b0[q]; PB1p[q] = b1[q]; PB2p[q] = b2[q];
        }
        #pragma unroll
        for (int c = 0; c < CH8; c++) mwr[c] = smw[c];
    }

    int lane = tid & 31;
    int l16  = lane & 15;
    int half = lane >> 4;                           // 0 or 1
    int w    = tid >> 5;                            // warp in block
    int p0   = (blockIdx.x * 4 + w) * 8;            // 8 points per warp

    float m[8];

    #pragma unroll
    for (int pair = 0; pair < 4; pair++) {
        int pMine = p0 + pair*2 + half;
        int bbase = pMine & ~(NPTS - 1);            // b * N

        // center record (broadcast within half-warp): base pairs + p + Sp + em'
        const ulonglong2* cp = (const ulonglong2*)&g_ctr[(size_t)pMine*4];
        ulonglong2 c01 = cp[0];
        ulonglong2 c23 = cp[1];
        float4 cpp = ((const float4*)cp)[2];        // {px,py,pz,Sp}
        float  em  = ((const float*)cp)[12];        // em + K0
        u64 base2[4] = {c01.x, c01.y, c23.x, c23.y};

        // neighbor index + single 16B gather
        size_t off = (size_t)pMine * KNN + l16;
        int jv = is32 ? idx32[off] : (int)idx64[off];
        int j = bbase + jv;
        float4 a = *(const float4*)((const char*)g_nbr + ((size_t)(unsigned)j << 4));
        // |pn|^2 recomputed; mm rides in a.w
        float Sj = fmaf(a.x, a.x, fmaf(a.y, a.y, a.z*a.z));
        float t  = cpp.w + Sj - 2.f * (cpp.x*a.x + cpp.y*a.y + cpp.z*a.z);

        u64 tt = pk2(t, t);
        u64 ax = pk2(a.x, a.x), ay = pk2(a.y, a.y), az = pk2(a.z, a.z);
        float pt = 0.f;
        #pragma unroll
        for (int q = 0; q < 4; q++) {
            u64 h = base2[q];
            h = ff2(w02[q],  tt, h);
            h = ff2(ax, PB0p[q], h);
            h = ff2(ay, PB1p[q], h);
            h = ff2(az, PB2p[q], h);
            float hl, hh; up2(h, hl, hh);
            pt = fmaf(fmaxf(hl, 0.f), mwr[2*q],   pt);   // relu(point bn) . mw
            pt = fmaf(fmaxf(hh, 0.f), mwr[2*q+1], pt);
        }
        float g = fmaxf(pt + em + a.w, 0.f);        // relu(map bn)

        // stage (j, g) for this phase; then channel-per-lane gather/max
        sjg[w][pair][lane] = make_uint2((unsigned)j, __float_as_uint(g));
        __syncwarp();

        float mA = -3.402823466e38f, mB = -3.402823466e38f;
        #pragma unroll
        for (int k = 0; k < KNN; k++) {
            uint2 vA = sjg[w][pair][k];
            uint2 vB = sjg[w][pair][k + 16];
            float gA = __uint_as_float(vA.y);
            float gB = __uint_as_float(vB.y);
            float vAf = *(const float*)((const char*)g_gam + (((size_t)vA.x << 7) + ((unsigned)lane << 2)));
            float vBf = *(const float*)((const char*)g_gam + (((size_t)vB.x << 7) + ((unsigned)lane << 2)));
            mA = fmaxf(mA, gA * vAf);
            mB = fmaxf(mB, gB * vBf);
        }
        m[pair*2]     = mA;
        m[pair*2 + 1] = mB;
    }

    // stage m matrix: lane (= channel) writes its 8 point-values
    *(float4*)&sm[w][lane][0] = make_float4(m[0], m[1], m[2], m[3]);
    *(float4*)&sm[w][lane][4] = make_float4(m[4], m[5], m[6], m[7]);
    __syncwarp();

    // fc for 8 points, two points packed per f32x2 lane
    u64 accx[4], accy[4], accz[4], accw[4];
    #pragma unroll
    for (int p = 0; p < 4; p++) { accx[p] = 0; accy[p] = 0; accz[p] = 0; accw[p] = 0; }
    #pragma unroll
    for (int c = 0; c < CH32; c++) {
        float4 wv = sfc[c*32 + lane];
        float4 ma = *(const float4*)&sm[w][c][0];
        float4 mb = *(const float4*)&sm[w][c][4];
        u64 wxx = pk2(wv.x, wv.x), wyy = pk2(wv.y, wv.y);
        u64 wzz = pk2(wv.z, wv.z), www = pk2(wv.w, wv.w);
        u64 mp[4] = {pk2(ma.x, ma.y), pk2(ma.z, ma.w),
                     pk2(mb.x, mb.y), pk2(mb.z, mb.w)};
        #pragma unroll
        for (int p = 0; p < 4; p++) {
            accx[p] = ff2(mp[p], wxx, accx[p]);
            accy[p] = ff2(mp[p], wyy, accy[p]);
            accz[p] = ff2(mp[p], wzz, accz[p]);
            accw[p] = ff2(mp[p], www, accw[p]);
        }
    }
    float4* op = (float4*)out + (size_t)p0 * 32 + lane;
    #pragma unroll
    for (int p = 0; p < 4; p++) {
        float x0, x1, y0, y1, z0, z1, w0, w1;
        up2(accx[p], x0, x1); up2(accy[p], y0, y1);
        up2(accz[p], z0, z1); up2(accw[p], w0, w1);
        op[(2*p)*32]   = make_float4(x0, y0, z0, w0);
        op[(2*p+1)*32] = make_float4(x1, y1, z1, w1);
    }
}

extern "C" void kernel_launch(void* const* d_in, const int* in_sizes, int n_in,
                              void* d_out, int out_size)
{
    const float* feats    = (const float*)d_in[0];
    const void*  idx_raw  = (const void*)d_in[1];
    const float* point_W  = (const float*)d_in[2];
    const float* point_bn = (const float*)d_in[3];
    const float* eta_W    = (const float*)d_in[4];
    const float* eta_bn   = (const float*)d_in[5];
    const float* mu_W     = (const float*)d_in[6];
    const float* mu_bn    = (const float*)d_in[7];
    const float* gamma_W  = (const float*)d_in[8];
    const float* gamma_bn = (const float*)d_in[9];
    const float* map_W    = (const float*)d_in[10];
    const float* map_bn   = (const float*)d_in[11];
    const float* fc_W     = (const float*)d_in[12];
    float* out = (float*)d_out;

    pass1_kernel<<<ROWS/256, 128>>>(feats, point_W, point_bn, eta_W, eta_bn,
                                    mu_W, mu_bn, gamma_W, gamma_bn,
                                    map_W, map_bn);
    // 8 points/warp * 4 warps/block = 32 points/block
    pass2_kernel<<<ROWS/32, 128>>>(idx_raw, fc_W, out,
                                   point_W, point_bn, map_W, map_bn);
}

// round 8
// speedup vs baseline: 1.8377x; 1.0556x over previous
#include <cuda_runtime.h>

#define NPTS   65536
#define BATCH  2
#define ROWS   (BATCH*NPTS)
#define DIM    35
#define KNN    16
#define CH8    8
#define CH32   32
#define OUTCH  128
#define EPSF   1e-5f

typedef unsigned long long u64;

// packed fp32x2 helpers (FFMA2 — ptxas never emits these from C++)
__device__ __forceinline__ u64 pk2(float lo, float hi) {
    u64 r; asm("mov.b64 %0, {%1, %2};" : "=l"(r) : "f"(lo), "f"(hi)); return r;
}
__device__ __forceinline__ void up2(u64 v, float& lo, float& hi) {
    asm("mov.b64 {%0, %1}, %2;" : "=f"(lo), "=f"(hi) : "l"(v));
}
__device__ __forceinline__ u64 ff2(u64 a, u64 b, u64 c) {
    u64 d; asm("fma.rn.f32x2 %0, %1, %2, %3;" : "=l"(d) : "l"(a), "l"(b), "l"(c)); return d;
}

// Pass-1 outputs
__device__ __align__(16) float  g_gam[(size_t)ROWS*CH32];  // 16.8 MB, L2-resident
__device__ __align__(16) float4 g_nbr[ROWS];               // {pn.x,pn.y,pn.z,mm}
// center record: {base[0..3]},{base[4..7]},{px,py,pz,em+K0} = 48B/row
__device__ __align__(16) float4 g_ctr[(size_t)ROWS*3];

// ---------------------------------------------------------------------------
// Pass 1: per-row precompute — gam[32], base[8], em', mm, pn.
// ---------------------------------------------------------------------------
__global__ void __launch_bounds__(128) pass1_kernel(
    const float* __restrict__ feats,
    const float* __restrict__ point_W, const float* __restrict__ point_bn,
    const float* __restrict__ eta_W,   const float* __restrict__ eta_bn,
    const float* __restrict__ mu_W,    const float* __restrict__ mu_bn,
    const float* __restrict__ gamma_W, const float* __restrict__ gamma_bn,
    const float* __restrict__ map_W,   const float* __restrict__ map_bn)
{
    __shared__ __align__(16) float srow[256*DIM + 1];
    __shared__ __align__(16) float sW[DIM*CH32];
    __shared__ __align__(16) float stg[CH32];
    __shared__ __align__(16) float sPA[3*CH8], stp[CH8];
    __shared__ float su[32], sv[32];
    __shared__ float sK0;
    int tid = threadIdx.x;
    int R0  = blockIdx.x * 256;

    // stage 256 input rows coalesced
    const float4* src = (const float4*)feats + ((size_t)R0 * DIM >> 2);
    float4* dst = (float4*)srow;
    for (int i = tid; i < 256*DIM/4; i += 128) dst[i] = src[i];

    // per-block constant folding
    float s_map = map_bn[0] * rsqrtf(map_bn[3] + EPSF);
    for (int i = tid; i < DIM*CH32; i += 128) {
        int c = i & 31;
        float sg = gamma_bn[0*CH32+c] * rsqrtf(gamma_bn[3*CH32+c] + EPSF);
        sW[i] = gamma_W[i] * sg;
    }
    if (tid < CH32) {
        int c = tid;
        float sg = gamma_bn[0*CH32+c] * rsqrtf(gamma_bn[3*CH32+c] + EPSF);
        stg[c] = gamma_bn[1*CH32+c] - gamma_bn[2*CH32+c] * sg;
    }
    if (tid >= 32 && tid < 64) {
        int i = tid - 32;
        float suv = 0.f, svv = 0.f;
        for (int c = 0; c < CH8; c++) {
            float se  = eta_bn[0*CH8+c] * rsqrtf(eta_bn[3*CH8+c] + EPSF);
            float smu = mu_bn [0*CH8+c] * rsqrtf(mu_bn [3*CH8+c] + EPSF);
            suv += eta_W[i*CH8+c] * se  * (map_W[1*CH8+c] * s_map);
            svv += mu_W [i*CH8+c] * smu * (map_W[2*CH8+c] * s_map);
        }
        su[i] = suv;
        sv[i] = svv;
    }
    if (tid >= 64 && tid < 64+CH8) {
        int c = tid - 64;
        float sp = point_bn[0*CH8+c] * rsqrtf(point_bn[3*CH8+c] + EPSF);
        stp[c] = point_bn[1*CH8+c] - point_bn[2*CH8+c] * sp;
        #pragma unroll
        for (int i = 0; i < 3; i++)
            sPA[i*CH8+c] = (point_W[(1+i)*CH8+c] + point_W[(7+i)*CH8+c]) * sp;
    }
    if (tid == 96) {
        float k0 = map_bn[1] - map_bn[2] * s_map;
        for (int c = 0; c < CH8; c++) {
            float se  = eta_bn[0*CH8+c] * rsqrtf(eta_bn[3*CH8+c] + EPSF);
            float te  = eta_bn[1*CH8+c] - eta_bn[2*CH8+c] * se;
            float smu = mu_bn [0*CH8+c] * rsqrtf(mu_bn [3*CH8+c] + EPSF);
            float tmu = mu_bn [1*CH8+c] - mu_bn [2*CH8+c] * smu;
            k0 += te  * map_W[1*CH8+c] * s_map;
            k0 += tmu * map_W[2*CH8+c] * s_map;
        }
        sK0 = k0;
    }
    __syncthreads();

    // packed accumulators: 16 f32x2 per row
    u64 acc0[16], acc1[16];
    const u64* stg2 = (const u64*)stg;
    #pragma unroll
    for (int q = 0; q < 16; q++) { acc0[q] = stg2[q]; acc1[q] = stg2[q]; }

    const float* r0 = &srow[tid * DIM];
    const float* r1 = &srow[(tid + 128) * DIM];
    float pn0[3], pn1[3];
    float e0 = 0.f, e1 = 0.f, m0 = 0.f, m1 = 0.f;

    #pragma unroll
    for (int d = 0; d < 3; d++) {
        float f0 = r0[d], f1 = r1[d];
        pn0[d] = f0; pn1[d] = f1;
        u64 pf0 = pk2(f0, f0), pf1 = pk2(f1, f1);
        const u64* w2 = (const u64*)&sW[d*CH32];
        #pragma unroll
        for (int q = 0; q < 16; q++) {
            u64 w = w2[q];
            acc0[q] = ff2(pf0, w, acc0[q]);
            acc1[q] = ff2(pf1, w, acc1[q]);
        }
    }
    for (int d = 3; d < DIM; d++) {
        float f0 = r0[d], f1 = r1[d];
        float uu = su[d-3], vw = sv[d-3];
        e0 = fmaf(f0, uu, e0); e1 = fmaf(f1, uu, e1);
        m0 = fmaf(f0, vw, m0); m1 = fmaf(f1, vw, m1);
        u64 pf0 = pk2(f0, f0), pf1 = pk2(f1, f1);
        const u64* w2 = (const u64*)&sW[d*CH32];
        #pragma unroll
        for (int q = 0; q < 16; q++) {
            u64 w = w2[q];
            acc0[q] = ff2(pf0, w, acc0[q]);
            acc1[q] = ff2(pf1, w, acc1[q]);
        }
    }

    // base[c] = tp[c] + p.PA  (packed in channel pairs)
    u64 b0p[4], b1p[4];
    {
        const u64* tp2 = (const u64*)stp;
        const u64* pa0 = (const u64*)&sPA[0];
        const u64* pa1 = (const u64*)&sPA[CH8];
        const u64* pa2 = (const u64*)&sPA[2*CH8];
        u64 x0 = pk2(pn0[0], pn0[0]), y0 = pk2(pn0[1], pn0[1]), z0 = pk2(pn0[2], pn0[2]);
        u64 x1 = pk2(pn1[0], pn1[0]), y1 = pk2(pn1[1], pn1[1]), z1 = pk2(pn1[2], pn1[2]);
        #pragma unroll
        for (int q = 0; q < 4; q++) {
            u64 h0 = tp2[q], h1 = tp2[q];
            h0 = ff2(x0, pa0[q], h0); h1 = ff2(x1, pa0[q], h1);
            h0 = ff2(y0, pa1[q], h0); h1 = ff2(y1, pa1[q], h1);
            h0 = ff2(z0, pa2[q], h0); h1 = ff2(z1, pa2[q], h1);
            b0p[q] = h0; b1p[q] = h1;
        }
    }

    int gr0 = R0 + tid, gr1 = R0 + tid + 128;
    ulonglong2* gp0 = (ulonglong2*)&g_gam[(size_t)gr0 * CH32];
    ulonglong2* gp1 = (ulonglong2*)&g_gam[(size_t)gr1 * CH32];
    #pragma unroll
    for (int q = 0; q < 8; q++) {
        gp0[q] = make_ulonglong2(acc0[2*q], acc0[2*q+1]);
        gp1[q] = make_ulonglong2(acc1[2*q], acc1[2*q+1]);
    }
    g_nbr[gr0] = make_float4(pn0[0], pn0[1], pn0[2], m0);
    g_nbr[gr1] = make_float4(pn1[0], pn1[1], pn1[2], m1);
    float K0 = sK0;
    float4* cp0 = &g_ctr[(size_t)gr0*3];
    float4* cp1 = &g_ctr[(size_t)gr1*3];
    {
        float bl, bh;
        up2(b0p[0], bl, bh); float b00 = bl, b01 = bh;
        up2(b0p[1], bl, bh); float b02 = bl, b03 = bh;
        cp0[0] = make_float4(b00, b01, b02, b03);
        up2(b0p[2], bl, bh); b00 = bl; b01 = bh;
        up2(b0p[3], bl, bh); b02 = bl; b03 = bh;
        cp0[1] = make_float4(b00, b01, b02, b03);
        cp0[2] = make_float4(pn0[0], pn0[1], pn0[2], e0 + K0);
        up2(b1p[0], bl, bh); b00 = bl; b01 = bh;
        up2(b1p[1], bl, bh); b02 = bl; b03 = bh;
        cp1[0] = make_float4(b00, b01, b02, b03);
        up2(b1p[2], bl, bh); b00 = bl; b01 = bh;
        up2(b1p[3], bl, bh); b02 = bl; b03 = bh;
        cp1[1] = make_float4(b00, b01, b02, b03);
        cp1[2] = make_float4(pn1[0], pn1[1], pn1[2], e1 + K0);
    }
}

// ---------------------------------------------------------------------------
// Pass 2: warp = 8 consecutive points. All 4 phases' idx + nbr gathers are
// prefetched up front (MLP ~12/warp); all (j,g) staged before a single
// __syncwarp(); then all gam-gather loops batch; then one fc loop.
// ---------------------------------------------------------------------------
__global__ void __launch_bounds__(128, 4) pass2_kernel(
    const void* __restrict__ idx_raw,
    const float* __restrict__ fcW, float* __restrict__ out,
    const float* __restrict__ point_W, const float* __restrict__ point_bn,
    const float* __restrict__ map_W,   const float* __restrict__ map_bn)
{
    __shared__ __align__(16) float4 sfc[CH32*32];     // fc_W (32x128) = 16 KB
    __shared__ __align__(16) float  sm[4][32][8];     // m matrix, 4 KB
    __shared__ __align__(8)  uint2  sjg[4][4][32];    // (j,g) per phase, 4 KB
    __shared__ __align__(16) float  sw0[CH8], sPB[3*CH8];
    __shared__ float smw[CH8];
    __shared__ int   sIs32;

    int tid = threadIdx.x;
    const float4* fsrc = (const float4*)fcW;
    #pragma unroll
    for (int i = 0; i < 8; i++) sfc[tid + 128*i] = fsrc[tid + 128*i];

    if (tid < 32) {
        const long long* i64 = (const long long*)idx_raw;
        long long v = i64[tid];
        unsigned bad = __ballot_sync(0xffffffffu, v < 0 || v >= NPTS);
        if (tid == 0) sIs32 = bad ? 1 : 0;
        float s_map = map_bn[0] * rsqrtf(map_bn[3] + EPSF);
        if (tid < CH8) {
            int c = tid;
            float sp = point_bn[0*CH8+c] * rsqrtf(point_bn[3*CH8+c] + EPSF);
            sw0[c] = point_W[0*CH8+c] * sp;
            #pragma unroll
            for (int i = 0; i < 3; i++)
                sPB[i*CH8+c] = (point_W[(4+i)*CH8+c] - point_W[(7+i)*CH8+c]) * sp;
            smw[c] = map_W[c] * s_map;
        }
    }
    __syncthreads();

    const int is32 = sIs32;
    const int*       idx32 = (const int*)idx_raw;
    const long long* idx64 = (const long long*)idx_raw;

    // packed channel-pair constants
    u64 w02[4], PB0p[4], PB1p[4], PB2p[4];
    float mwr[CH8];
    {
        const u64* a  = (const u64*)sw0;
        const u64* b0 = (const u64*)&sPB[0];
        const u64* b1 = (const u64*)&sPB[CH8];
        const u64* b2 = (const u64*)&sPB[2*CH8];
        #pragma unroll
        for (int q = 0; q < 4; q++) {
            w02[q] = a[q]; PB0p[q] = b0[q]; PB1p[q] = b1[q]; PB2p[q] = b2[q];
        }
        #pragma unroll
        for (int c = 0; c < CH8; c++) mwr[c] = smw[c];
    }

    int lane = tid & 31;
    int l16  = lane & 15;
    int half = lane >> 4;                           // 0 or 1
    int w    = tid >> 5;                            // warp in block
    int p0   = (blockIdx.x * 4 + w) * 8;            // 8 points per warp

    // ---- prefetch: all 4 phases' idx, then all 4 nbr gathers ----
    int jv[4];
    #pragma unroll
    for (int pair = 0; pair < 4; pair++) {
        int pM = p0 + pair*2 + half;
        size_t off = (size_t)pM * KNN + l16;
        int v = is32 ? idx32[off] : (int)idx64[off];
        jv[pair] = (pM & ~(NPTS - 1)) + v;
    }
    float4 a4[4];
    #pragma unroll
    for (int pair = 0; pair < 4; pair++)
        a4[pair] = *(const float4*)((const char*)g_nbr + ((size_t)(unsigned)jv[pair] << 4));

    // ---- compute g for all 4 phases, stage (j,g) ----
    #pragma unroll
    for (int pair = 0; pair < 4; pair++) {
        int pM = p0 + pair*2 + half;
        const float4* cp = &g_ctr[(size_t)pM*3];
        float4 cb0 = cp[0];
        float4 cb1 = cp[1];
        float4 cpf = cp[2];                          // {px,py,pz,em+K0}
        u64 base2[4] = { pk2(cb0.x, cb0.y), pk2(cb0.z, cb0.w),
                         pk2(cb1.x, cb1.y), pk2(cb1.z, cb1.w) };

        float4 a = a4[pair];
        float dx = cpf.x - a.x, dy = cpf.y - a.y, dz = cpf.z - a.z;
        float t  = fmaf(dx, dx, fmaf(dy, dy, dz*dz));   // |p-pn|^2 (matches ref)

        u64 tt = pk2(t, t);
        u64 ax = pk2(a.x, a.x), ay = pk2(a.y, a.y), az = pk2(a.z, a.z);
        float pt = 0.f;
        #pragma unroll
        for (int q = 0; q < 4; q++) {
            u64 h = base2[q];
            h = ff2(w02[q],  tt, h);
            h = ff2(ax, PB0p[q], h);
            h = ff2(ay, PB1p[q], h);
            h = ff2(az, PB2p[q], h);
            float hl, hh; up2(h, hl, hh);
            pt = fmaf(fmaxf(hl, 0.f), mwr[2*q],   pt);   // relu(point bn) . mw
            pt = fmaf(fmaxf(hh, 0.f), mwr[2*q+1], pt);
        }
        float g = fmaxf(pt + cpf.w + a.w, 0.f);          // relu(map bn)
        sjg[w][pair][lane] = make_uint2((unsigned)jv[pair], __float_as_uint(g));
    }
    __syncwarp();

    // ---- gam gather + max for all 4 phases (loads batch across phases) ----
    float m[8];
    #pragma unroll
    for (int pair = 0; pair < 4; pair++) {
        float mA = -3.402823466e38f, mB = -3.402823466e38f;
        #pragma unroll
        for (int k = 0; k < KNN; k++) {
            uint2 vA = sjg[w][pair][k];
            uint2 vB = sjg[w][pair][k + 16];
            float gA = __uint_as_float(vA.y);
            float gB = __uint_as_float(vB.y);
            float vAf = *(const float*)((const char*)g_gam + (((size_t)vA.x << 7) + ((unsigned)lane << 2)));
            float vBf = *(const float*)((const char*)g_gam + (((size_t)vB.x << 7) + ((unsigned)lane << 2)));
            mA = fmaxf(mA, gA * vAf);
            mB = fmaxf(mB, gB * vBf);
        }
        m[pair*2]     = mA;
        m[pair*2 + 1] = mB;
    }

    // stage m matrix: lane (= channel) writes its 8 point-values
    *(float4*)&sm[w][lane][0] = make_float4(m[0], m[1], m[2], m[3]);
    *(float4*)&sm[w][lane][4] = make_float4(m[4], m[5], m[6], m[7]);
    __syncwarp();

    // fc for 8 points, two points packed per f32x2 lane
    u64 accx[4], accy[4], accz[4], accw[4];
    #pragma unroll
    for (int p = 0; p < 4; p++) { accx[p] = 0; accy[p] = 0; accz[p] = 0; accw[p] = 0; }
    #pragma unroll
    for (int c = 0; c < CH32; c++) {
        float4 wv = sfc[c*32 + lane];
        float4 ma = *(const float4*)&sm[w][c][0];
        float4 mb = *(const float4*)&sm[w][c][4];
        u64 wxx = pk2(wv.x, wv.x), wyy = pk2(wv.y, wv.y);
        u64 wzz = pk2(wv.z, wv.z), www = pk2(wv.w, wv.w);
        u64 mp[4] = {pk2(ma.x, ma.y), pk2(ma.z, ma.w),
                     pk2(mb.x, mb.y), pk2(mb.z, mb.w)};
        #pragma unroll
        for (int p = 0; p < 4; p++) {
            accx[p] = ff2(mp[p], wxx, accx[p]);
            accy[p] = ff2(mp[p], wyy, accy[p]);
            accz[p] = ff2(mp[p], wzz, accz[p]);
            accw[p] = ff2(mp[p], www, accw[p]);
        }
    }
    float4* op = (float4*)out + (size_t)p0 * 32 + lane;
    #pragma unroll
    for (int p = 0; p < 4; p++) {
        float x0, x1, y0, y1, z0, z1, w0, w1;
        up2(accx[p], x0, x1); up2(accy[p], y0, y1);
        up2(accz[p], z0, z1); up2(accw[p], w0, w1);
        op[(2*p)*32]   = make_float4(x0, y0, z0, w0);
        op[(2*p+1)*32] = make_float4(x1, y1, z1, w1);
    }
}

extern "C" void kernel_launch(void* const* d_in, const int* in_sizes, int n_in,
                              void* d_out, int out_size)
{
    const float* feats    = (const float*)d_in[0];
    const void*  idx_raw  = (const void*)d_in[1];
    const float* point_W  = (const float*)d_in[2];
    const float* point_bn = (const float*)d_in[3];
    const float* eta_W    = (const float*)d_in[4];
    const float* eta_bn   = (const float*)d_in[5];
    const float* mu_W     = (const float*)d_in[6];
    const float* mu_bn    = (const float*)d_in[7];
    const float* gamma_W  = (const float*)d_in[8];
    const float* gamma_bn = (const float*)d_in[9];
    const float* map_W    = (const float*)d_in[10];
    const float* map_bn   = (const float*)d_in[11];
    const float* fc_W     = (const float*)d_in[12];
    float* out = (float*)d_out;

    pass1_kernel<<<ROWS/256, 128>>>(feats, point_W, point_bn, eta_W, eta_bn,
                                    mu_W, mu_bn, gamma_W, gamma_bn,
                                    map_W, map_bn);
    // 8 points/warp * 4 warps/block = 32 points/block
    pass2_kernel<<<ROWS/32, 128>>>(idx_raw, fc_W, out,
                                   point_W, point_bn, map_W, map_bn);
}

// round 9
// speedup vs baseline: 1.9693x; 1.0716x over previous
#include <cuda_runtime.h>

#define NPTS   65536
#define BATCH  2
#define ROWS   (BATCH*NPTS)
#define DIM    35
#define KNN    16
#define CH8    8
#define CH32   32
#define OUTCH  128
#define EPSF   1e-5f

typedef unsigned long long u64;

// packed fp32x2 helpers (FFMA2/FMUL2 — ptxas never emits these from C++)
__device__ __forceinline__ u64 pk2(float lo, float hi) {
    u64 r; asm("mov.b64 %0, {%1, %2};" : "=l"(r) : "f"(lo), "f"(hi)); return r;
}
__device__ __forceinline__ void up2(u64 v, float& lo, float& hi) {
    asm("mov.b64 {%0, %1}, %2;" : "=f"(lo), "=f"(hi) : "l"(v));
}
__device__ __forceinline__ u64 ff2(u64 a, u64 b, u64 c) {
    u64 d; asm("fma.rn.f32x2 %0, %1, %2, %3;" : "=l"(d) : "l"(a), "l"(b), "l"(c)); return d;
}
__device__ __forceinline__ u64 fm2(u64 a, u64 b) {
    u64 d; asm("mul.rn.f32x2 %0, %1, %2;" : "=l"(d) : "l"(a), "l"(b)); return d;
}

// Pass-1 outputs
__device__ __align__(16) float  g_gam[(size_t)ROWS*CH32];  // 16.8 MB, L2-resident
__device__ __align__(16) float4 g_nbr[ROWS];               // {pn.x,pn.y,pn.z,mm}
// center record: {base[0..3]},{base[4..7]},{px,py,pz,em+K0} = 48B/row
__device__ __align__(16) float4 g_ctr[(size_t)ROWS*3];

// ---------------------------------------------------------------------------
// Pass 1: per-row precompute — gam[32], base[8], em', mm, pn.
// ---------------------------------------------------------------------------
__global__ void __launch_bounds__(128) pass1_kernel(
    const float* __restrict__ feats,
    const float* __restrict__ point_W, const float* __restrict__ point_bn,
    const float* __restrict__ eta_W,   const float* __restrict__ eta_bn,
    const float* __restrict__ mu_W,    const float* __restrict__ mu_bn,
    const float* __restrict__ gamma_W, const float* __restrict__ gamma_bn,
    const float* __restrict__ map_W,   const float* __restrict__ map_bn)
{
    __shared__ __align__(16) float srow[256*DIM + 1];
    __shared__ __align__(16) float sW[DIM*CH32];
    __shared__ __align__(16) float stg[CH32];
    __shared__ __align__(16) float sPA[3*CH8], stp[CH8];
    __shared__ float su[32], sv[32];
    __shared__ float sK0;
    int tid = threadIdx.x;
    int R0  = blockIdx.x * 256;

    const float4* src = (const float4*)feats + ((size_t)R0 * DIM >> 2);
    float4* dst = (float4*)srow;
    for (int i = tid; i < 256*DIM/4; i += 128) dst[i] = src[i];

    float s_map = map_bn[0] * rsqrtf(map_bn[3] + EPSF);
    for (int i = tid; i < DIM*CH32; i += 128) {
        int c = i & 31;
        float sg = gamma_bn[0*CH32+c] * rsqrtf(gamma_bn[3*CH32+c] + EPSF);
        sW[i] = gamma_W[i] * sg;
    }
    if (tid < CH32) {
        int c = tid;
        float sg = gamma_bn[0*CH32+c] * rsqrtf(gamma_bn[3*CH32+c] + EPSF);
        stg[c] = gamma_bn[1*CH32+c] - gamma_bn[2*CH32+c] * sg;
    }
    if (tid >= 32 && tid < 64) {
        int i = tid - 32;
        float suv = 0.f, svv = 0.f;
        for (int c = 0; c < CH8; c++) {
            float se  = eta_bn[0*CH8+c] * rsqrtf(eta_bn[3*CH8+c] + EPSF);
            float smu = mu_bn [0*CH8+c] * rsqrtf(mu_bn [3*CH8+c] + EPSF);
            suv += eta_W[i*CH8+c] * se  * (map_W[1*CH8+c] * s_map);
            svv += mu_W [i*CH8+c] * smu * (map_W[2*CH8+c] * s_map);
        }
        su[i] = suv;
        sv[i] = svv;
    }
    if (tid >= 64 && tid < 64+CH8) {
        int c = tid - 64;
        float sp = point_bn[0*CH8+c] * rsqrtf(point_bn[3*CH8+c] + EPSF);
        stp[c] = point_bn[1*CH8+c] - point_bn[2*CH8+c] * sp;
        #pragma unroll
        for (int i = 0; i < 3; i++)
            sPA[i*CH8+c] = (point_W[(1+i)*CH8+c] + point_W[(7+i)*CH8+c]) * sp;
    }
    if (tid == 96) {
        float k0 = map_bn[1] - map_bn[2] * s_map;
        for (int c = 0; c < CH8; c++) {
            float se  = eta_bn[0*CH8+c] * rsqrtf(eta_bn[3*CH8+c] + EPSF);
            float te  = eta_bn[1*CH8+c] - eta_bn[2*CH8+c] * se;
            float smu = mu_bn [0*CH8+c] * rsqrtf(mu_bn [3*CH8+c] + EPSF);
            float tmu = mu_bn [1*CH8+c] - mu_bn [2*CH8+c] * smu;
            k0 += te  * map_W[1*CH8+c] * s_map;
            k0 += tmu * map_W[2*CH8+c] * s_map;
        }
        sK0 = k0;
    }
    __syncthreads();

    u64 acc0[16], acc1[16];
    const u64* stg2 = (const u64*)stg;
    #pragma unroll
    for (int q = 0; q < 16; q++) { acc0[q] = stg2[q]; acc1[q] = stg2[q]; }

    const float* r0 = &srow[tid * DIM];
    const float* r1 = &srow[(tid + 128) * DIM];
    float pn0[3], pn1[3];
    float e0 = 0.f, e1 = 0.f, m0 = 0.f, m1 = 0.f;

    #pragma unroll
    for (int d = 0; d < 3; d++) {
        float f0 = r0[d], f1 = r1[d];
        pn0[d] = f0; pn1[d] = f1;
        u64 pf0 = pk2(f0, f0), pf1 = pk2(f1, f1);
        const u64* w2 = (const u64*)&sW[d*CH32];
        #pragma unroll
        for (int q = 0; q < 16; q++) {
            u64 w = w2[q];
            acc0[q] = ff2(pf0, w, acc0[q]);
            acc1[q] = ff2(pf1, w, acc1[q]);
        }
    }
    for (int d = 3; d < DIM; d++) {
        float f0 = r0[d], f1 = r1[d];
        float uu = su[d-3], vw = sv[d-3];
        e0 = fmaf(f0, uu, e0); e1 = fmaf(f1, uu, e1);
        m0 = fmaf(f0, vw, m0); m1 = fmaf(f1, vw, m1);
        u64 pf0 = pk2(f0, f0), pf1 = pk2(f1, f1);
        const u64* w2 = (const u64*)&sW[d*CH32];
        #pragma unroll
        for (int q = 0; q < 16; q++) {
            u64 w = w2[q];
            acc0[q] = ff2(pf0, w, acc0[q]);
            acc1[q] = ff2(pf1, w, acc1[q]);
        }
    }

    u64 b0p[4], b1p[4];
    {
        const u64* tp2 = (const u64*)stp;
        const u64* pa0 = (const u64*)&sPA[0];
        const u64* pa1 = (const u64*)&sPA[CH8];
        const u64* pa2 = (const u64*)&sPA[2*CH8];
        u64 x0 = pk2(pn0[0], pn0[0]), y0 = pk2(pn0[1], pn0[1]), z0 = pk2(pn0[2], pn0[2]);
        u64 x1 = pk2(pn1[0], pn1[0]), y1 = pk2(pn1[1], pn1[1]), z1 = pk2(pn1[2], pn1[2]);
        #pragma unroll
        for (int q = 0; q < 4; q++) {
            u64 h0 = tp2[q], h1 = tp2[q];
            h0 = ff2(x0, pa0[q], h0); h1 = ff2(x1, pa0[q], h1);
            h0 = ff2(y0, pa1[q], h0); h1 = ff2(y1, pa1[q], h1);
            h0 = ff2(z0, pa2[q], h0); h1 = ff2(z1, pa2[q], h1);
            b0p[q] = h0; b1p[q] = h1;
        }
    }

    int gr0 = R0 + tid, gr1 = R0 + tid + 128;
    ulonglong2* gp0 = (ulonglong2*)&g_gam[(size_t)gr0 * CH32];
    ulonglong2* gp1 = (ulonglong2*)&g_gam[(size_t)gr1 * CH32];
    #pragma unroll
    for (int q = 0; q < 8; q++) {
        gp0[q] = make_ulonglong2(acc0[2*q], acc0[2*q+1]);
        gp1[q] = make_ulonglong2(acc1[2*q], acc1[2*q+1]);
    }
    g_nbr[gr0] = make_float4(pn0[0], pn0[1], pn0[2], m0);
    g_nbr[gr1] = make_float4(pn1[0], pn1[1], pn1[2], m1);
    float K0 = sK0;
    float4* cp0 = &g_ctr[(size_t)gr0*3];
    float4* cp1 = &g_ctr[(size_t)gr1*3];
    {
        float bl, bh;
        up2(b0p[0], bl, bh); float b00 = bl, b01 = bh;
        up2(b0p[1], bl, bh); float b02 = bl, b03 = bh;
        cp0[0] = make_float4(b00, b01, b02, b03);
        up2(b0p[2], bl, bh); b00 = bl; b01 = bh;
        up2(b0p[3], bl, bh); b02 = bl; b03 = bh;
        cp0[1] = make_float4(b00, b01, b02, b03);
        cp0[2] = make_float4(pn0[0], pn0[1], pn0[2], e0 + K0);
        up2(b1p[0], bl, bh); b00 = bl; b01 = bh;
        up2(b1p[1], bl, bh); b02 = bl; b03 = bh;
        cp1[0] = make_float4(b00, b01, b02, b03);
        up2(b1p[2], bl, bh); b00 = bl; b01 = bh;
        up2(b1p[3], bl, bh); b02 = bl; b03 = bh;
        cp1[1] = make_float4(b00, b01, b02, b03);
        cp1[2] = make_float4(pn1[0], pn1[1], pn1[2], e1 + K0);
    }
}

// ---------------------------------------------------------------------------
// Pass 2: warp = 8 points. Prefetched idx/nbr; half-warp-split gam loop with
// LDG.64 channel pairs + uint4 sjg reads; SHFL mini-transpose; one fc loop.
// ---------------------------------------------------------------------------
__global__ void __launch_bounds__(128, 5) pass2_kernel(
    const void* __restrict__ idx_raw,
    const float* __restrict__ fcW, float* __restrict__ out,
    const float* __restrict__ point_W, const float* __restrict__ point_bn,
    const float* __restrict__ map_W,   const float* __restrict__ map_bn)
{
    __shared__ __align__(16) float4 sfc[CH32*32];     // fc_W (32x128) = 16 KB
    __shared__ __align__(16) float  sm[4][32][8];     // m matrix, 4 KB
    __shared__ __align__(16) uint2  sjg[4][4][36];    // (j,g), stride-18 per half
    __shared__ __align__(16) float  sw0[CH8], sPB[3*CH8];
    __shared__ float smw[CH8];
    __shared__ int   sIs32;

    int tid = threadIdx.x;
    const float4* fsrc = (const float4*)fcW;
    #pragma unroll
    for (int i = 0; i < 8; i++) sfc[tid + 128*i] = fsrc[tid + 128*i];

    if (tid < 32) {
        const long long* i64 = (const long long*)idx_raw;
        long long v = i64[tid];
        unsigned bad = __ballot_sync(0xffffffffu, v < 0 || v >= NPTS);
        if (tid == 0) sIs32 = bad ? 1 : 0;
        float s_map = map_bn[0] * rsqrtf(map_bn[3] + EPSF);
        if (tid < CH8) {
            int c = tid;
            float sp = point_bn[0*CH8+c] * rsqrtf(point_bn[3*CH8+c] + EPSF);
            sw0[c] = point_W[0*CH8+c] * sp;
            #pragma unroll
            for (int i = 0; i < 3; i++)
                sPB[i*CH8+c] = (point_W[(4+i)*CH8+c] - point_W[(7+i)*CH8+c]) * sp;
            smw[c] = map_W[c] * s_map;
        }
    }
    __syncthreads();

    const int is32 = sIs32;
    const int*       idx32 = (const int*)idx_raw;
    const long long* idx64 = (const long long*)idx_raw;

    u64 w02[4], PB0p[4], PB1p[4], PB2p[4];
    float mwr[CH8];
    {
        const u64* a  = (const u64*)sw0;
        const u64* b0 = (const u64*)&sPB[0];
        const u64* b1 = (const u64*)&sPB[CH8];
        const u64* b2 = (const u64*)&sPB[2*CH8];
        #pragma unroll
        for (int q = 0; q < 4; q++) {
            w02[q] = a[q]; PB0p[q] = b0[q]; PB1p[q] = b1[q]; PB2p[q] = b2[q];
        }
        #pragma unroll
        for (int c = 0; c < CH8; c++) mwr[c] = smw[c];
    }

    int lane = tid & 31;
    int l16  = lane & 15;
    int half = lane >> 4;                           // 0 or 1
    int w    = tid >> 5;                            // warp in block
    int p0   = (blockIdx.x * 4 + w) * 8;            // 8 points per warp

    // ---- prefetch: all 4 phases' idx, then all 4 nbr gathers ----
    int jv[4];
    #pragma unroll
    for (int pair = 0; pair < 4; pair++) {
        int pM = p0 + pair*2 + half;
        size_t off = (size_t)pM * KNN + l16;
        int v = is32 ? idx32[off] : (int)idx64[off];
        jv[pair] = (pM & ~(NPTS - 1)) + v;
    }
    float4 a4[4];
    #pragma unroll
    for (int pair = 0; pair < 4; pair++)
        a4[pair] = *(const float4*)((const char*)g_nbr + ((size_t)(unsigned)jv[pair] << 4));

    // ---- compute g for all 4 phases, stage (j,g) at stride-18 per half ----
    #pragma unroll
    for (int pair = 0; pair < 4; pair++) {
        int pM = p0 + pair*2 + half;
        const float4* cp = &g_ctr[(size_t)pM*3];
        float4 cb0 = cp[0];
        float4 cb1 = cp[1];
        float4 cpf = cp[2];                          // {px,py,pz,em+K0}
        u64 base2[4] = { pk2(cb0.x, cb0.y), pk2(cb0.z, cb0.w),
                         pk2(cb1.x, cb1.y), pk2(cb1.z, cb1.w) };

        float4 a = a4[pair];
        float dx = cpf.x - a.x, dy = cpf.y - a.y, dz = cpf.z - a.z;
        float t  = fmaf(dx, dx, fmaf(dy, dy, dz*dz));   // |p-pn|^2

        u64 tt = pk2(t, t);
        u64 ax = pk2(a.x, a.x), ay = pk2(a.y, a.y), az = pk2(a.z, a.z);
        float pt = 0.f;
        #pragma unroll
        for (int q = 0; q < 4; q++) {
            u64 h = base2[q];
            h = ff2(w02[q],  tt, h);
            h = ff2(ax, PB0p[q], h);
            h = ff2(ay, PB1p[q], h);
            h = ff2(az, PB2p[q], h);
            float hl, hh; up2(h, hl, hh);
            pt = fmaf(fmaxf(hl, 0.f), mwr[2*q],   pt);
            pt = fmaf(fmaxf(hh, 0.f), mwr[2*q+1], pt);
        }
        float g = fmaxf(pt + cpf.w + a.w, 0.f);          // relu(map bn)
        sjg[w][pair][18*half + l16] = make_uint2((unsigned)jv[pair], __float_as_uint(g));
    }
    __syncwarp();

    // ---- gam gather + max: half-warp per point, u64 channel pair per lane ----
    // lane (half, c0=l16) accumulates channels {2c0, 2c0+1} of point 2*pair+half.
    int c0 = l16;
    float m[8];
    #pragma unroll
    for (int pair = 0; pair < 4; pair++) {
        const uint4* jg4 = (const uint4*)&sjg[w][pair][18*half];
        float alo = -3.402823466e38f, ahi = -3.402823466e38f;
        #pragma unroll
        for (int k2 = 0; k2 < KNN/2; k2++) {
            uint4 jg = jg4[k2];                     // neighbors 2k2, 2k2+1
            u64 v0 = *(const u64*)((const char*)g_gam + (((size_t)jg.x << 7) + ((unsigned)c0 << 3)));
            u64 v1 = *(const u64*)((const char*)g_gam + (((size_t)jg.z << 7) + ((unsigned)c0 << 3)));
            float g0 = __uint_as_float(jg.y);
            float g1 = __uint_as_float(jg.w);
            u64 q0 = fm2(v0, pk2(g0, g0));
            u64 q1 = fm2(v1, pk2(g1, g1));
            float q0l, q0h, q1l, q1h;
            up2(q0, q0l, q0h); up2(q1, q1l, q1h);
            alo = fmaxf(alo, fmaxf(q0l, q1l));
            ahi = fmaxf(ahi, fmaxf(q0h, q1h));
        }
        // mini-transpose: lane (=channel c) collects m for points 2*pair, 2*pair+1
        int srcl = lane >> 1;
        float vl0 = __shfl_sync(0xffffffffu, alo, srcl);
        float vh0 = __shfl_sync(0xffffffffu, ahi, srcl);
        float vl1 = __shfl_sync(0xffffffffu, alo, srcl + 16);
        float vh1 = __shfl_sync(0xffffffffu, ahi, srcl + 16);
        m[pair*2]     = (lane & 1) ? vh0 : vl0;
        m[pair*2 + 1] = (lane & 1) ? vh1 : vl1;
    }

    // stage m matrix: lane (= channel) writes its 8 point-values
    *(float4*)&sm[w][lane][0] = make_float4(m[0], m[1], m[2], m[3]);
    *(float4*)&sm[w][lane][4] = make_float4(m[4], m[5], m[6], m[7]);
    __syncwarp();

    // fc for 8 points, two points packed per f32x2 lane
    u64 accx[4], accy[4], accz[4], accw[4];
    #pragma unroll
    for (int p = 0; p < 4; p++) { accx[p] = 0; accy[p] = 0; accz[p] = 0; accw[p] = 0; }
    #pragma unroll
    for (int c = 0; c < CH32; c++) {
        float4 wv = sfc[c*32 + lane];
        float4 ma = *(const float4*)&sm[w][c][0];
        float4 mb = *(const float4*)&sm[w][c][4];
        u64 wxx = pk2(wv.x, wv.x), wyy = pk2(wv.y, wv.y);
        u64 wzz = pk2(wv.z, wv.z), www = pk2(wv.w, wv.w);
        u64 mp[4] = {pk2(ma.x, ma.y), pk2(ma.z, ma.w),
                     pk2(mb.x, mb.y), pk2(mb.z, mb.w)};
        #pragma unroll
        for (int p = 0; p < 4; p++) {
            accx[p] = ff2(mp[p], wxx, accx[p]);
            accy[p] = ff2(mp[p], wyy, accy[p]);
            accz[p] = ff2(mp[p], wzz, accz[p]);
            accw[p] = ff2(mp[p], www, accw[p]);
        }
    }
    float4* op = (float4*)out + (size_t)p0 * 32 + lane;
    #pragma unroll
    for (int p = 0; p < 4; p++) {
        float x0, x1, y0, y1, z0, z1, w0, w1;
        up2(accx[p], x0, x1); up2(accy[p], y0, y1);
        up2(accz[p], z0, z1); up2(accw[p], w0, w1);
        op[(2*p)*32]   = make_float4(x0, y0, z0, w0);
        op[(2*p+1)*32] = make_float4(x1, y1, z1, w1);
    }
}

extern "C" void kernel_launch(void* const* d_in, const int* in_sizes, int n_in,
                              void* d_out, int out_size)
{
    const float* feats    = (const float*)d_in[0];
    const void*  idx_raw  = (const void*)d_in[1];
    const float* point_W  = (const float*)d_in[2];
    const float* point_bn = (const float*)d_in[3];
    const float* eta_W    = (const float*)d_in[4];
    const float* eta_bn   = (const float*)d_in[5];
    const float* mu_W     = (const float*)d_in[6];
    const float* mu_bn    = (const float*)d_in[7];
    const float* gamma_W  = (const float*)d_in[8];
    const float* gamma_bn = (const float*)d_in[9];
    const float* map_W    = (const float*)d_in[10];
    const float* map_bn   = (const float*)d_in[11];
    const float* fc_W     = (const float*)d_in[12];
    float* out = (float*)d_out;

    pass1_kernel<<<ROWS/256, 128>>>(feats, point_W, point_bn, eta_W, eta_bn,
                                    mu_W, mu_bn, gamma_W, gamma_bn,
                                    map_W, map_bn);
    // 8 points/warp * 4 warps/block = 32 points/block
    pass2_kernel<<<ROWS/32, 128>>>(idx_raw, fc_W, out,
                                   point_W, point_bn, map_W, map_bn);
}

// round 10
// speedup vs baseline: 2.0674x; 1.0498x over previous
#include <cuda_runtime.h>

#define NPTS   65536
#define BATCH  2
#define ROWS   (BATCH*NPTS)
#define DIM    35
#define KNN    16
#define CH8    8
#define CH32   32
#define OUTCH  128
#define EPSF   1e-5f

typedef unsigned long long u64;

// packed fp32x2 helpers (FFMA2/FMUL2 — ptxas never emits these from C++)
__device__ __forceinline__ u64 pk2(float lo, float hi) {
    u64 r; asm("mov.b64 %0, {%1, %2};" : "=l"(r) : "f"(lo), "f"(hi)); return r;
}
__device__ __forceinline__ void up2(u64 v, float& lo, float& hi) {
    asm("mov.b64 {%0, %1}, %2;" : "=f"(lo), "=f"(hi) : "l"(v));
}
__device__ __forceinline__ u64 ff2(u64 a, u64 b, u64 c) {
    u64 d; asm("fma.rn.f32x2 %0, %1, %2, %3;" : "=l"(d) : "l"(a), "l"(b), "l"(c)); return d;
}
__device__ __forceinline__ u64 fm2(u64 a, u64 b) {
    u64 d; asm("mul.rn.f32x2 %0, %1, %2;" : "=l"(d) : "l"(a), "l"(b)); return d;
}

// Pass-1 outputs
__device__ __align__(16) float  g_gam[(size_t)ROWS*CH32];  // 16.8 MB, L2-resident
__device__ __align__(16) float4 g_nbr[ROWS];               // {pn.x,pn.y,pn.z,mm}
// center record: {base[0..3]},{base[4..7]},{px,py,pz,em+K0} = 48B/row
__device__ __align__(16) float4 g_ctr[(size_t)ROWS*3];

// ---------------------------------------------------------------------------
// Pass 1: per-row precompute — gam[32], base[8], em', mm, pn.
// ---------------------------------------------------------------------------
__global__ void __launch_bounds__(128) pass1_kernel(
    const float* __restrict__ feats,
    const float* __restrict__ point_W, const float* __restrict__ point_bn,
    const float* __restrict__ eta_W,   const float* __restrict__ eta_bn,
    const float* __restrict__ mu_W,    const float* __restrict__ mu_bn,
    const float* __restrict__ gamma_W, const float* __restrict__ gamma_bn,
    const float* __restrict__ map_W,   const float* __restrict__ map_bn)
{
    __shared__ __align__(16) float srow[256*DIM + 1];
    __shared__ __align__(16) float sW[DIM*CH32];
    __shared__ __align__(16) float stg[CH32];
    __shared__ __align__(16) float sPA[3*CH8], stp[CH8];
    __shared__ float su[32], sv[32];
    __shared__ float sK0;
    int tid = threadIdx.x;
    int R0  = blockIdx.x * 256;

    const float4* src = (const float4*)feats + ((size_t)R0 * DIM >> 2);
    float4* dst = (float4*)srow;
    for (int i = tid; i < 256*DIM/4; i += 128) dst[i] = src[i];

    float s_map = map_bn[0] * rsqrtf(map_bn[3] + EPSF);
    for (int i = tid; i < DIM*CH32; i += 128) {
        int c = i & 31;
        float sg = gamma_bn[0*CH32+c] * rsqrtf(gamma_bn[3*CH32+c] + EPSF);
        sW[i] = gamma_W[i] * sg;
    }
    if (tid < CH32) {
        int c = tid;
        float sg = gamma_bn[0*CH32+c] * rsqrtf(gamma_bn[3*CH32+c] + EPSF);
        stg[c] = gamma_bn[1*CH32+c] - gamma_bn[2*CH32+c] * sg;
    }
    if (tid >= 32 && tid < 64) {
        int i = tid - 32;
        float suv = 0.f, svv = 0.f;
        for (int c = 0; c < CH8; c++) {
            float se  = eta_bn[0*CH8+c] * rsqrtf(eta_bn[3*CH8+c] + EPSF);
            float smu = mu_bn [0*CH8+c] * rsqrtf(mu_bn [3*CH8+c] + EPSF);
            suv += eta_W[i*CH8+c] * se  * (map_W[1*CH8+c] * s_map);
            svv += mu_W [i*CH8+c] * smu * (map_W[2*CH8+c] * s_map);
        }
        su[i] = suv;
        sv[i] = svv;
    }
    if (tid >= 64 && tid < 64+CH8) {
        int c = tid - 64;
        float sp = point_bn[0*CH8+c] * rsqrtf(point_bn[3*CH8+c] + EPSF);
        stp[c] = point_bn[1*CH8+c] - point_bn[2*CH8+c] * sp;
        #pragma unroll
        for (int i = 0; i < 3; i++)
            sPA[i*CH8+c] = (point_W[(1+i)*CH8+c] + point_W[(7+i)*CH8+c]) * sp;
    }
    if (tid == 96) {
        float k0 = map_bn[1] - map_bn[2] * s_map;
        for (int c = 0; c < CH8; c++) {
            float se  = eta_bn[0*CH8+c] * rsqrtf(eta_bn[3*CH8+c] + EPSF);
            float te  = eta_bn[1*CH8+c] - eta_bn[2*CH8+c] * se;
            float smu = mu_bn [0*CH8+c] * rsqrtf(mu_bn [3*CH8+c] + EPSF);
            float tmu = mu_bn [1*CH8+c] - mu_bn [2*CH8+c] * smu;
            k0 += te  * map_W[1*CH8+c] * s_map;
            k0 += tmu * map_W[2*CH8+c] * s_map;
        }
        sK0 = k0;
    }
    __syncthreads();

    u64 acc0[16], acc1[16];
    const u64* stg2 = (const u64*)stg;
    #pragma unroll
    for (int q = 0; q < 16; q++) { acc0[q] = stg2[q]; acc1[q] = stg2[q]; }

    const float* r0 = &srow[tid * DIM];
    const float* r1 = &srow[(tid + 128) * DIM];
    float pn0[3], pn1[3];
    float e0 = 0.f, e1 = 0.f, m0 = 0.f, m1 = 0.f;

    #pragma unroll
    for (int d = 0; d < 3; d++) {
        float f0 = r0[d], f1 = r1[d];
        pn0[d] = f0; pn1[d] = f1;
        u64 pf0 = pk2(f0, f0), pf1 = pk2(f1, f1);
        const u64* w2 = (const u64*)&sW[d*CH32];
        #pragma unroll
        for (int q = 0; q < 16; q++) {
            u64 w = w2[q];
            acc0[q] = ff2(pf0, w, acc0[q]);
            acc1[q] = ff2(pf1, w, acc1[q]);
        }
    }
    for (int d = 3; d < DIM; d++) {
        float f0 = r0[d], f1 = r1[d];
        float uu = su[d-3], vw = sv[d-3];
        e0 = fmaf(f0, uu, e0); e1 = fmaf(f1, uu, e1);
        m0 = fmaf(f0, vw, m0); m1 = fmaf(f1, vw, m1);
        u64 pf0 = pk2(f0, f0), pf1 = pk2(f1, f1);
        const u64* w2 = (const u64*)&sW[d*CH32];
        #pragma unroll
        for (int q = 0; q < 16; q++) {
            u64 w = w2[q];
            acc0[q] = ff2(pf0, w, acc0[q]);
            acc1[q] = ff2(pf1, w, acc1[q]);
        }
    }

    u64 b0p[4], b1p[4];
    {
        const u64* tp2 = (const u64*)stp;
        const u64* pa0 = (const u64*)&sPA[0];
        const u64* pa1 = (const u64*)&sPA[CH8];
        const u64* pa2 = (const u64*)&sPA[2*CH8];
        u64 x0 = pk2(pn0[0], pn0[0]), y0 = pk2(pn0[1], pn0[1]), z0 = pk2(pn0[2], pn0[2]);
        u64 x1 = pk2(pn1[0], pn1[0]), y1 = pk2(pn1[1], pn1[1]), z1 = pk2(pn1[2], pn1[2]);
        #pragma unroll
        for (int q = 0; q < 4; q++) {
            u64 h0 = tp2[q], h1 = tp2[q];
            h0 = ff2(x0, pa0[q], h0); h1 = ff2(x1, pa0[q], h1);
            h0 = ff2(y0, pa1[q], h0); h1 = ff2(y1, pa1[q], h1);
            h0 = ff2(z0, pa2[q], h0); h1 = ff2(z1, pa2[q], h1);
            b0p[q] = h0; b1p[q] = h1;
        }
    }

    int gr0 = R0 + tid, gr1 = R0 + tid + 128;
    ulonglong2* gp0 = (ulonglong2*)&g_gam[(size_t)gr0 * CH32];
    ulonglong2* gp1 = (ulonglong2*)&g_gam[(size_t)gr1 * CH32];
    #pragma unroll
    for (int q = 0; q < 8; q++) {
        gp0[q] = make_ulonglong2(acc0[2*q], acc0[2*q+1]);
        gp1[q] = make_ulonglong2(acc1[2*q], acc1[2*q+1]);
    }
    g_nbr[gr0] = make_float4(pn0[0], pn0[1], pn0[2], m0);
    g_nbr[gr1] = make_float4(pn1[0], pn1[1], pn1[2], m1);
    float K0 = sK0;
    float4* cp0 = &g_ctr[(size_t)gr0*3];
    float4* cp1 = &g_ctr[(size_t)gr1*3];
    {
        float bl, bh;
        up2(b0p[0], bl, bh); float b00 = bl, b01 = bh;
        up2(b0p[1], bl, bh); float b02 = bl, b03 = bh;
        cp0[0] = make_float4(b00, b01, b02, b03);
        up2(b0p[2], bl, bh); b00 = bl; b01 = bh;
        up2(b0p[3], bl, bh); b02 = bl; b03 = bh;
        cp0[1] = make_float4(b00, b01, b02, b03);
        cp0[2] = make_float4(pn0[0], pn0[1], pn0[2], e0 + K0);
        up2(b1p[0], bl, bh); b00 = bl; b01 = bh;
        up2(b1p[1], bl, bh); b02 = bl; b03 = bh;
        cp1[0] = make_float4(b00, b01, b02, b03);
        up2(b1p[2], bl, bh); b00 = bl; b01 = bh;
        up2(b1p[3], bl, bh); b02 = bl; b03 = bh;
        cp1[1] = make_float4(b00, b01, b02, b03);
        cp1[2] = make_float4(pn1[0], pn1[1], pn1[2], e1 + K0);
    }
}

// ---------------------------------------------------------------------------
// Pass 2: warp = 16 points (8 half-warp pair phases). Prefetched idx/nbr;
// half-warp-split gam loop (LDG.64 channel pairs, uint4 sjg reads); SHFL
// mini-transpose into padded smem m-matrix; ONE fc sweep serves all 16 points.
// ---------------------------------------------------------------------------
#define NPAIR 8
#define SMSTR 20   // padded m-row stride (floats): 16B-aligned, 4-way max conflicts

__global__ void __launch_bounds__(128, 4) pass2_kernel(
    const void* __restrict__ idx_raw,
    const float* __restrict__ fcW, float* __restrict__ out,
    const float* __restrict__ point_W, const float* __restrict__ point_bn,
    const float* __restrict__ map_W,   const float* __restrict__ map_bn)
{
    __shared__ __align__(16) float4 sfc[CH32*32];       // fc_W (32x128) = 16 KB
    __shared__ __align__(16) float  sm[4][CH32][SMSTR]; // m matrix, 10 KB
    __shared__ __align__(16) uint2  sjg[4][NPAIR][36];  // (j,g), stride-18/half, 9 KB
    __shared__ __align__(16) float  sw0[CH8], sPB[3*CH8];
    __shared__ float smw[CH8];
    __shared__ int   sIs32;

    int tid = threadIdx.x;
    const float4* fsrc = (const float4*)fcW;
    #pragma unroll
    for (int i = 0; i < 8; i++) sfc[tid + 128*i] = fsrc[tid + 128*i];

    if (tid < 32) {
        const long long* i64 = (const long long*)idx_raw;
        long long v = i64[tid];
        unsigned bad = __ballot_sync(0xffffffffu, v < 0 || v >= NPTS);
        if (tid == 0) sIs32 = bad ? 1 : 0;
        float s_map = map_bn[0] * rsqrtf(map_bn[3] + EPSF);
        if (tid < CH8) {
            int c = tid;
            float sp = point_bn[0*CH8+c] * rsqrtf(point_bn[3*CH8+c] + EPSF);
            sw0[c] = point_W[0*CH8+c] * sp;
            #pragma unroll
            for (int i = 0; i < 3; i++)
                sPB[i*CH8+c] = (point_W[(4+i)*CH8+c] - point_W[(7+i)*CH8+c]) * sp;
            smw[c] = map_W[c] * s_map;
        }
    }
    __syncthreads();

    const int is32 = sIs32;
    const int*       idx32 = (const int*)idx_raw;
    const long long* idx64 = (const long long*)idx_raw;

    u64 w02[4], PB0p[4], PB1p[4], PB2p[4];
    float mwr[CH8];
    {
        const u64* a  = (const u64*)sw0;
        const u64* b0 = (const u64*)&sPB[0];
        const u64* b1 = (const u64*)&sPB[CH8];
        const u64* b2 = (const u64*)&sPB[2*CH8];
        #pragma unroll
        for (int q = 0; q < 4; q++) {
            w02[q] = a[q]; PB0p[q] = b0[q]; PB1p[q] = b1[q]; PB2p[q] = b2[q];
        }
        #pragma unroll
        for (int c = 0; c < CH8; c++) mwr[c] = smw[c];
    }

    int lane = tid & 31;
    int l16  = lane & 15;
    int half = lane >> 4;                            // 0 or 1
    int w    = tid >> 5;                             // warp in block
    int p0   = (blockIdx.x * 4 + w) * 16;            // 16 points per warp

    // ---- prefetch: all 8 phases' idx, then all 8 nbr gathers ----
    int jv[NPAIR];
    #pragma unroll
    for (int pair = 0; pair < NPAIR; pair++) {
        int pM = p0 + pair*2 + half;
        size_t off = (size_t)pM * KNN + l16;
        int v = is32 ? idx32[off] : (int)idx64[off];
        jv[pair] = (pM & ~(NPTS - 1)) + v;
    }
    float4 a4[NPAIR];
    #pragma unroll
    for (int pair = 0; pair < NPAIR; pair++)
        a4[pair] = *(const float4*)((const char*)g_nbr + ((size_t)(unsigned)jv[pair] << 4));

    // ---- phase A: compute g for all 8 phases, stage (j,g) ----
    #pragma unroll
    for (int pair = 0; pair < NPAIR; pair++) {
        int pM = p0 + pair*2 + half;
        const float4* cp = &g_ctr[(size_t)pM*3];
        float4 cb0 = cp[0];
        float4 cb1 = cp[1];
        float4 cpf = cp[2];                          // {px,py,pz,em+K0}
        u64 base2[4] = { pk2(cb0.x, cb0.y), pk2(cb0.z, cb0.w),
                         pk2(cb1.x, cb1.y), pk2(cb1.z, cb1.w) };

        float4 a = a4[pair];
        float dx = cpf.x - a.x, dy = cpf.y - a.y, dz = cpf.z - a.z;
        float t  = fmaf(dx, dx, fmaf(dy, dy, dz*dz));   // |p-pn|^2

        u64 tt = pk2(t, t);
        u64 ax = pk2(a.x, a.x), ay = pk2(a.y, a.y), az = pk2(a.z, a.z);
        float pt = 0.f;
        #pragma unroll
        for (int q = 0; q < 4; q++) {
            u64 h = base2[q];
            h = ff2(w02[q],  tt, h);
            h = ff2(ax, PB0p[q], h);
            h = ff2(ay, PB1p[q], h);
            h = ff2(az, PB2p[q], h);
            float hl, hh; up2(h, hl, hh);
            pt = fmaf(fmaxf(hl, 0.f), mwr[2*q],   pt);
            pt = fmaf(fmaxf(hh, 0.f), mwr[2*q+1], pt);
        }
        float g = fmaxf(pt + cpf.w + a.w, 0.f);          // relu(map bn)
        sjg[w][pair][18*half + l16] = make_uint2((unsigned)jv[pair], __float_as_uint(g));
    }
    __syncwarp();

    // ---- phase B: gam gather + max, transpose, write m to smem ----
    int c0 = l16;
    #pragma unroll
    for (int pair = 0; pair < NPAIR; pair++) {
        const uint4* jg4 = (const uint4*)&sjg[w][pair][18*half];
        float alo = -3.402823466e38f, ahi = -3.402823466e38f;
        #pragma unroll
        for (int k2 = 0; k2 < KNN/2; k2++) {
            uint4 jg = jg4[k2];                     // neighbors 2k2, 2k2+1
            u64 v0 = *(const u64*)((const char*)g_gam + (((size_t)jg.x << 7) + ((unsigned)c0 << 3)));
            u64 v1 = *(const u64*)((const char*)g_gam + (((size_t)jg.z << 7) + ((unsigned)c0 << 3)));
            float g0 = __uint_as_float(jg.y);
            float g1 = __uint_as_float(jg.w);
            u64 q0 = fm2(v0, pk2(g0, g0));
            u64 q1 = fm2(v1, pk2(g1, g1));
            float q0l, q0h, q1l, q1h;
            up2(q0, q0l, q0h); up2(q1, q1l, q1h);
            alo = fmaxf(alo, fmaxf(q0l, q1l));
            ahi = fmaxf(ahi, fmaxf(q0h, q1h));
        }
        // mini-transpose: lane (= channel) collects points 2*pair, 2*pair+1
        int srcl = lane >> 1;
        float vl0 = __shfl_sync(0xffffffffu, alo, srcl);
        float vh0 = __shfl_sync(0xffffffffu, ahi, srcl);
        float vl1 = __shfl_sync(0xffffffffu, alo, srcl + 16);
        float vh1 = __shfl_sync(0xffffffffu, ahi, srcl + 16);
        float mp0 = (lane & 1) ? vh0 : vl0;
        float mp1 = (lane & 1) ? vh1 : vl1;
        *(float2*)&sm[w][lane][2*pair] = make_float2(mp0, mp1);
    }
    __syncwarp();

    // ---- fc for 16 points: one sfc sweep, 8 point-pair f32x2 accumulators ----
    u64 accx[NPAIR], accy[NPAIR], accz[NPAIR], accw[NPAIR];
    #pragma unroll
    for (int p = 0; p < NPAIR; p++) { accx[p] = 0; accy[p] = 0; accz[p] = 0; accw[p] = 0; }
    #pragma unroll
    for (int c = 0; c < CH32; c++) {
        float4 wv = sfc[c*32 + lane];
        float4 ma = *(const float4*)&sm[w][c][0];
        float4 mb = *(const float4*)&sm[w][c][4];
        float4 mc = *(const float4*)&sm[w][c][8];
        float4 md = *(const float4*)&sm[w][c][12];
        u64 wxx = pk2(wv.x, wv.x), wyy = pk2(wv.y, wv.y);
        u64 wzz = pk2(wv.z, wv.z), www = pk2(wv.w, wv.w);
        u64 mp[NPAIR] = {pk2(ma.x, ma.y), pk2(ma.z, ma.w),
                         pk2(mb.x, mb.y), pk2(mb.z, mb.w),
                         pk2(mc.x, mc.y), pk2(mc.z, mc.w),
                         pk2(md.x, md.y), pk2(md.z, md.w)};
        #pragma unroll
        for (int p = 0; p < NPAIR; p++) {
            accx[p] = ff2(mp[p], wxx, accx[p]);
            accy[p] = ff2(mp[p], wyy, accy[p]);
            accz[p] = ff2(mp[p], wzz, accz[p]);
            accw[p] = ff2(mp[p], www, accw[p]);
        }
    }
    float4* op = (float4*)out + (size_t)p0 * 32 + lane;
    #pragma unroll
    for (int p = 0; p < NPAIR; p++) {
        float x0, x1, y0, y1, z0, z1, w0, w1;
        up2(accx[p], x0, x1); up2(accy[p], y0, y1);
        up2(accz[p], z0, z1); up2(accw[p], w0, w1);
        op[(2*p)*32]   = make_float4(x0, y0, z0, w0);
        op[(2*p+1)*32] = make_float4(x1, y1, z1, w1);
    }
}

extern "C" void kernel_launch(void* const* d_in, const int* in_sizes, int n_in,
                              void* d_out, int out_size)
{
    const float* feats    = (const float*)d_in[0];
    const void*  idx_raw  = (const void*)d_in[1];
    const float* point_W  = (const float*)d_in[2];
    const float* point_bn = (const float*)d_in[3];
    const float* eta_W    = (const float*)d_in[4];
    const float* eta_bn   = (const float*)d_in[5];
    const float* mu_W     = (const float*)d_in[6];
    const float* mu_bn    = (const float*)d_in[7];
    const float* gamma_W  = (const float*)d_in[8];
    const float* gamma_bn = (const float*)d_in[9];
    const float* map_W    = (const float*)d_in[10];
    const float* map_bn   = (const float*)d_in[11];
    const float* fc_W     = (const float*)d_in[12];
    float* out = (float*)d_out;

    pass1_kernel<<<ROWS/256, 128>>>(feats, point_W, point_bn, eta_W, eta_bn,
                                    mu_W, mu_bn, gamma_W, gamma_bn,
                                    map_W, map_bn);
    // 16 points/warp * 4 warps/block = 64 points/block
    pass2_kernel<<<ROWS/64, 128>>>(idx_raw, fc_W, out,
                                   point_W, point_bn, map_W, map_bn);
}